// round 8
// baseline (speedup 1.0000x reference)
#include <cuda_runtime.h>
#include <cuda_bf16.h>
#include <stdint.h>
#include <math.h>

// Problem constants
#define NB   2
#define HH   8
#define TT   1024
#define HID  64
#define NHB  (NB*HH)
#define D2   (2*HID)
#define EMB  (HH*HID)          // 512
#define LCH  64
#define NCH  (TT/LCH)          // 16
#define CTX_ELEMS (NB*HH*TT*HID)
#define ANG_K 0.0015339807878856412f

typedef unsigned long long u64t;

__device__ __forceinline__ u64t pack2(float lo, float hi) {
    u64t r; asm("mov.b64 %0, {%1, %2};" : "=l"(r) : "f"(lo), "f"(hi)); return r;
}
__device__ __forceinline__ float2 unpack2(u64t p) {
    float2 r; asm("mov.b64 {%0, %1}, %2;" : "=f"(r.x), "=f"(r.y) : "l"(p)); return r;
}
__device__ __forceinline__ void fma2(u64t& d, u64t a, u64t b) {
    asm("fma.rn.f32x2 %0, %1, %2, %0;" : "+l"(d) : "l"(a), "l"(b));
}
__device__ __forceinline__ void mul2(u64t& d, u64t a, u64t b) {
    asm("mul.rn.f32x2 %0, %1, %2;" : "=l"(d) : "l"(a), "l"(b));
}
__device__ __forceinline__ uint32_t smem_u32(const void* p) {
    uint32_t a;
    asm("{ .reg .u64 t; cvta.to.shared.u64 t, %1; cvt.u32.u64 %0, t; }" : "=r"(a) : "l"(p));
    return a;
}

// ---- sm_80-class warp MMA helpers (base PTX, no 'a' features) ----
__device__ __forceinline__ void ldsm_x4(uint32_t& r0, uint32_t& r1, uint32_t& r2, uint32_t& r3,
                                        uint32_t addr) {
    asm volatile("ldmatrix.sync.aligned.m8n8.x4.shared.b16 {%0,%1,%2,%3}, [%4];"
                 : "=r"(r0), "=r"(r1), "=r"(r2), "=r"(r3) : "r"(addr));
}
__device__ __forceinline__ void ldsm_x2(uint32_t& r0, uint32_t& r1, uint32_t addr) {
    asm volatile("ldmatrix.sync.aligned.m8n8.x2.shared.b16 {%0,%1}, [%2];"
                 : "=r"(r0), "=r"(r1) : "r"(addr));
}
__device__ __forceinline__ void mma_bf16(float* c, const uint32_t* a, const uint32_t* b) {
    asm volatile("mma.sync.aligned.m16n8k16.row.col.f32.bf16.bf16.f32 "
                 "{%0,%1,%2,%3}, {%4,%5,%6,%7}, {%8,%9}, {%0,%1,%2,%3};"
                 : "+f"(c[0]), "+f"(c[1]), "+f"(c[2]), "+f"(c[3])
                 : "r"(a[0]), "r"(a[1]), "r"(a[2]), "r"(a[3]), "r"(b[0]), "r"(b[1]));
}
// split fp32 -> bf16 hi + bf16 residual
__device__ __forceinline__ void split4(float4 x, uint32_t& h0, uint32_t& h1,
                                       uint32_t& l0, uint32_t& l1) {
    __nv_bfloat16 a = __float2bfloat16(x.x), b = __float2bfloat16(x.y),
                  c = __float2bfloat16(x.z), d = __float2bfloat16(x.w);
    __nv_bfloat162 hA(a, b), hB(c, d);
    h0 = *reinterpret_cast<uint32_t*>(&hA);
    h1 = *reinterpret_cast<uint32_t*>(&hB);
    __nv_bfloat162 lA(__float2bfloat16(x.x - __bfloat162float(a)),
                      __float2bfloat16(x.y - __bfloat162float(b)));
    __nv_bfloat162 lB(__float2bfloat16(x.z - __bfloat162float(c)),
                      __float2bfloat16(x.w - __bfloat162float(d)));
    l0 = *reinterpret_cast<uint32_t*>(&lA);
    l1 = *reinterpret_cast<uint32_t*>(&lB);
}

// Scratch (device globals)
__device__ float g_S   [NHB*NCH*D2*HID];
__device__ float g_P   [NHB*NCH*D2*HID];
__device__ float g_sk  [NHB*NCH*D2];
__device__ float g_skP [NHB*NCH*D2];
__device__ float g_attn[TT*NB*EMB];

// ---------------------------------------------------------------------------
// Kernel A: per-(b,chunk) sums (unchanged, passing since R5)
// ---------------------------------------------------------------------------
__global__ __launch_bounds__(256) void chunk_sums_kernel(const float* __restrict__ k,
                                                         const float* __restrict__ v) {
    extern __shared__ float sm[];
    float* sK   = sm;
    float* sV   = sm + 4096;
    float* sSin = sm + 8192;
    float* sCos = sm + 8256;
    const int b = blockIdx.x, c = blockIdx.y, tid = threadIdx.x;

    if (tid < LCH) {
        float ang = (float)(c * LCH + tid + 1) * ANG_K;
        sSin[tid] = sinf(ang);
        sCos[tid] = cosf(ang);
    }
    const float4* kg = reinterpret_cast<const float4*>(k + ((size_t)b * TT + c * LCH) * HID);
    float4* sK4w = reinterpret_cast<float4*>(sK);
    for (int i = tid; i < LCH * 16; i += 256) {
        float4 kv = kg[i];
        sK4w[i] = make_float4(fmaxf(kv.x, 0.f), fmaxf(kv.y, 0.f),
                              fmaxf(kv.z, 0.f), fmaxf(kv.w, 0.f));
    }
    const float4* vg = reinterpret_cast<const float4*>(v);
    float4* sV4w = reinterpret_cast<float4*>(sV);
    for (int i = tid; i < LCH * 16; i += 256) {
        int t = i >> 4, c4 = i & 15;
        sV4w[t * 16 + c4] = vg[((size_t)(c * LCH + t) * NHB + b) * 16 + c4];
    }
    __syncthreads();

    const int tx = tid & 15, ty = tid >> 4;
    const int m0 = tx * 4;
    const float* wT = (ty < 8) ? sSin : sCos;
    u64t acc[8][2];
#pragma unroll
    for (int i = 0; i < 8; ++i) { acc[i][0] = pack2(0.f, 0.f); acc[i][1] = pack2(0.f, 0.f); }

    const float4* sK4 = reinterpret_cast<const float4*>(sK);
    const float4* sV4 = reinterpret_cast<const float4*>(sV);
    for (int t = 0; t < LCH; ++t) {
        float4 a0 = sK4[t * 16 + (ty & 7) * 2];
        float4 a1 = sK4[t * 16 + (ty & 7) * 2 + 1];
        float4 bv = sV4[t * 16 + tx];
        float w = wT[t];
        u64t wp = pack2(w, w);
        u64t b01 = pack2(bv.x, bv.y), b23 = pack2(bv.z, bv.w);
        mul2(b01, b01, wp);
        mul2(b23, b23, wp);
        float av[8] = {a0.x, a0.y, a0.z, a0.w, a1.x, a1.y, a1.z, a1.w};
#pragma unroll
        for (int i = 0; i < 8; ++i) {
            u64t ad = pack2(av[i], av[i]);
            fma2(acc[i][0], ad, b01);
            fma2(acc[i][1], ad, b23);
        }
    }
    float* Sout = g_S + (size_t)(b * NCH + c) * (D2 * HID);
#pragma unroll
    for (int i = 0; i < 8; ++i) {
        float2 p0 = unpack2(acc[i][0]);
        float2 p1 = unpack2(acc[i][1]);
        *reinterpret_cast<float4*>(Sout + (ty * 8 + i) * HID + m0) =
            make_float4(p0.x, p0.y, p1.x, p1.y);
    }

    if (tid < D2) {
        int dl = tid & 63;
        const float* wv = (tid < 64) ? sSin : sCos;
        float s = 0.f;
        for (int t = 0; t < LCH; ++t) s += wv[t] * sK[t * HID + dl];
        g_sk[(b * NCH + c) * D2 + tid] = s;
    }
}

// ---------------------------------------------------------------------------
// Kernel B: exclusive prefix (unchanged)
// ---------------------------------------------------------------------------
__global__ __launch_bounds__(256) void prefix_kernel() {
    const int b = blockIdx.x, s = blockIdx.y, tid = threadIdx.x;
    size_t eoff = (size_t)s * 512 + tid * 2;
    float r0 = 0.f, r1 = 0.f;
#pragma unroll
    for (int c = 0; c < NCH; ++c) {
        size_t base = (size_t)(b * NCH + c) * (D2 * HID) + eoff;
        float2 sv = *reinterpret_cast<const float2*>(&g_S[base]);
        *reinterpret_cast<float2*>(&g_P[base]) = make_float2(r0, r1);
        r0 += sv.x; r1 += sv.y;
    }
    if (s == 0 && tid < D2) {
        float run = 0.f;
#pragma unroll
        for (int c = 0; c < NCH; ++c) {
            int idx = (b * NCH + c) * D2 + tid;
            g_skP[idx] = run;
            run += g_sk[idx];
        }
    }
}

// ---------------------------------------------------------------------------
// Kernel C: per-(b,chunk) output (unchanged)
// ---------------------------------------------------------------------------
__global__ __launch_bounds__(256, 3) void chunk_out_kernel(const float* __restrict__ q,
                                                           const float* __restrict__ k,
                                                           const float* __restrict__ v) {
    extern __shared__ float sm[];
    float* sQ   = sm;
    float* sB   = sm + 4096;
    float* sV   = sm + 8448;
    float* sS   = sm + 12544;
    float* sSin = sm + 16640;
    float* sCos = sm + 16704;
    float* sSkp = sm + 16768;
    float* sDen = sm + 16896;

    const int b = blockIdx.x, c = blockIdx.y, tid = threadIdx.x;
    const int lane = tid & 31, w = tid >> 5;

    if (tid < LCH) {
        float ang = (float)(c * LCH + tid + 1) * ANG_K;
        sSin[tid] = sinf(ang);
        sCos[tid] = cosf(ang);
    }
    if (tid < D2) sSkp[tid] = g_skP[(b * NCH + c) * D2 + tid];

    const float4* qg = reinterpret_cast<const float4*>(q + ((size_t)b * TT + c * LCH) * HID);
    const float4* kg = reinterpret_cast<const float4*>(k + ((size_t)b * TT + c * LCH) * HID);
    float4* sQ4w = reinterpret_cast<float4*>(sQ);
    float4* sB4w = reinterpret_cast<float4*>(sB);
    for (int i = tid; i < LCH * 16; i += 256) {
        int t = i >> 4, c4 = i & 15;
        float4 qv = qg[i];
        sQ4w[i] = make_float4(fmaxf(qv.x, 0.f), fmaxf(qv.y, 0.f),
                              fmaxf(qv.z, 0.f), fmaxf(qv.w, 0.f));
        float4 kv = kg[i];
        sB4w[t * 17 + c4] = make_float4(fmaxf(kv.x, 0.f), fmaxf(kv.y, 0.f),
                                        fmaxf(kv.z, 0.f), fmaxf(kv.w, 0.f));
    }
    const float4* vg = reinterpret_cast<const float4*>(v);
    float4* sV4w = reinterpret_cast<float4*>(sV);
    for (int i = tid; i < LCH * 16; i += 256) {
        int t = i >> 4, c4 = i & 15;
        sV4w[t * 16 + c4] = vg[((size_t)(c * LCH + t) * NHB + b) * 16 + c4];
    }
    __syncthreads();

    {
        const float4* sQ4 = reinterpret_cast<const float4*>(sQ);
        const float4* sK4 = reinterpret_cast<const float4*>(sB);
        const int r0 = w * 8;
        float acc0[8] = {0,0,0,0,0,0,0,0};
        float acc1[8] = {0,0,0,0,0,0,0,0};
        if (w < 4) {
            for (int d4 = 0; d4 < 16; ++d4) {
                float4 k0 = sK4[lane * 17 + d4];
#pragma unroll
                for (int i = 0; i < 8; ++i) {
                    float4 qv = sQ4[(r0 + i) * 16 + d4];
                    acc0[i] = fmaf(qv.x, k0.x, acc0[i]);
                    acc0[i] = fmaf(qv.y, k0.y, acc0[i]);
                    acc0[i] = fmaf(qv.z, k0.z, acc0[i]);
                    acc0[i] = fmaf(qv.w, k0.w, acc0[i]);
                }
            }
        } else {
            for (int d4 = 0; d4 < 16; ++d4) {
                float4 k0 = sK4[lane * 17 + d4];
                float4 k1 = sK4[(lane + 32) * 17 + d4];
#pragma unroll
                for (int i = 0; i < 8; ++i) {
                    float4 qv = sQ4[(r0 + i) * 16 + d4];
                    acc0[i] = fmaf(qv.x, k0.x, acc0[i]);
                    acc0[i] = fmaf(qv.y, k0.y, acc0[i]);
                    acc0[i] = fmaf(qv.z, k0.z, acc0[i]);
                    acc0[i] = fmaf(qv.w, k0.w, acc0[i]);
                    acc1[i] = fmaf(qv.x, k1.x, acc1[i]);
                    acc1[i] = fmaf(qv.y, k1.y, acc1[i]);
                    acc1[i] = fmaf(qv.z, k1.z, acc1[i]);
                    acc1[i] = fmaf(qv.w, k1.w, acc1[i]);
                }
            }
        }
        float sk0 = sSin[lane], ck0 = sCos[lane];
        float sk1 = sSin[lane + 32], ck1 = sCos[lane + 32];
#pragma unroll
        for (int i = 0; i < 8; ++i) {
            int r = r0 + i;
            float sr = sSin[r], cr = sCos[r];
            float f0 = cr * ck0 + sr * sk0;
            float f1 = cr * ck1 + sr * sk1;
            float v0 = (lane <= r)      ? acc0[i] * f0 : 0.f;
            float v1 = (lane + 32 <= r) ? acc1[i] * f1 : 0.f;
            sS[r * LCH + lane]      = v0;
            sS[r * LCH + lane + 32] = v1;
            float qra = sQ[r * HID + lane];
            float qrb = sQ[r * HID + lane + 32];
            float pl = sr * (qra * sSkp[lane] + qrb * sSkp[lane + 32])
                     + cr * (qra * sSkp[64 + lane] + qrb * sSkp[96 + lane]);
            float p = v0 + v1 + pl;
#pragma unroll
            for (int o = 16; o > 0; o >>= 1) p += __shfl_xor_sync(0xFFFFFFFFu, p, o);
            if (lane == 0) sDen[r] = fmaxf(p, 1e-6f);
        }
    }
    __syncthreads();

    {
        const int tx = tid & 15, ty = tid >> 4;
        const int r0 = ty * 4, m0 = tx * 4;
        const float4* sQ4 = reinterpret_cast<const float4*>(sQ);
        const float4* sS4 = reinterpret_cast<const float4*>(sS);
        const float4* sV4 = reinterpret_cast<const float4*>(sV);
        const float4* sP4 = reinterpret_cast<const float4*>(sB);
        const float4* Pg  = reinterpret_cast<const float4*>(
                                g_P + (size_t)(b * NCH + c) * (D2 * HID));
        float4* sPw = reinterpret_cast<float4*>(sB);

        u64t accS[4][2], accT[4][2];
#pragma unroll
        for (int i = 0; i < 4; ++i) { accS[i][0] = pack2(0.f,0.f); accS[i][1] = pack2(0.f,0.f); }

        for (int tp4 = 0; tp4 < 16; ++tp4) {
            float4 a[4];
#pragma unroll
            for (int i = 0; i < 4; ++i) a[i] = sS4[(r0 + i) * 16 + tp4];
            float4 b0 = sV4[(4 * tp4 + 0) * 16 + tx];
            float4 b1 = sV4[(4 * tp4 + 1) * 16 + tx];
            float4 b2 = sV4[(4 * tp4 + 2) * 16 + tx];
            float4 b3 = sV4[(4 * tp4 + 3) * 16 + tx];
            u64t b0l = pack2(b0.x,b0.y), b0h = pack2(b0.z,b0.w);
            u64t b1l = pack2(b1.x,b1.y), b1h = pack2(b1.z,b1.w);
            u64t b2l = pack2(b2.x,b2.y), b2h = pack2(b2.z,b2.w);
            u64t b3l = pack2(b3.x,b3.y), b3h = pack2(b3.z,b3.w);
#pragma unroll
            for (int i = 0; i < 4; ++i) {
                u64t ax = pack2(a[i].x, a[i].x); fma2(accS[i][0], ax, b0l); fma2(accS[i][1], ax, b0h);
                u64t ay = pack2(a[i].y, a[i].y); fma2(accS[i][0], ay, b1l); fma2(accS[i][1], ay, b1h);
                u64t az = pack2(a[i].z, a[i].z); fma2(accS[i][0], az, b2l); fma2(accS[i][1], az, b2h);
                u64t aw = pack2(a[i].w, a[i].w); fma2(accS[i][0], aw, b3l); fma2(accS[i][1], aw, b3h);
            }
        }
        __syncthreads();

#pragma unroll
        for (int half = 0; half < 2; ++half) {
            for (int i = tid; i < 1024; i += 256) {
                int row = i >> 4, c4 = i & 15;
                sPw[row * 17 + c4] = Pg[half * 1024 + i];
            }
            __syncthreads();
#pragma unroll
            for (int i = 0; i < 4; ++i) { accT[i][0] = pack2(0.f,0.f); accT[i][1] = pack2(0.f,0.f); }
            for (int d4 = 0; d4 < 16; ++d4) {
                float4 a[4];
#pragma unroll
                for (int i = 0; i < 4; ++i) a[i] = sQ4[(r0 + i) * 16 + d4];
                float4 b0 = sP4[(4 * d4 + 0) * 17 + tx];
                float4 b1 = sP4[(4 * d4 + 1) * 17 + tx];
                float4 b2 = sP4[(4 * d4 + 2) * 17 + tx];
                float4 b3 = sP4[(4 * d4 + 3) * 17 + tx];
                u64t b0l = pack2(b0.x,b0.y), b0h = pack2(b0.z,b0.w);
                u64t b1l = pack2(b1.x,b1.y), b1h = pack2(b1.z,b1.w);
                u64t b2l = pack2(b2.x,b2.y), b2h = pack2(b2.z,b2.w);
                u64t b3l = pack2(b3.x,b3.y), b3h = pack2(b3.z,b3.w);
#pragma unroll
                for (int i = 0; i < 4; ++i) {
                    u64t ax = pack2(a[i].x, a[i].x); fma2(accT[i][0], ax, b0l); fma2(accT[i][1], ax, b0h);
                    u64t ay = pack2(a[i].y, a[i].y); fma2(accT[i][0], ay, b1l); fma2(accT[i][1], ay, b1h);
                    u64t az = pack2(a[i].z, a[i].z); fma2(accT[i][0], az, b2l); fma2(accT[i][1], az, b2h);
                    u64t aw = pack2(a[i].w, a[i].w); fma2(accT[i][0], aw, b3l); fma2(accT[i][1], aw, b3h);
                }
            }
            const float* wT = half ? sCos : sSin;
#pragma unroll
            for (int i = 0; i < 4; ++i) {
                float wv = wT[r0 + i];
                u64t wd = pack2(wv, wv);
                fma2(accS[i][0], wd, accT[i][0]);
                fma2(accS[i][1], wd, accT[i][1]);
            }
            if (half == 0) __syncthreads();
        }

        const int n = b >> 3, h = b & 7;
#pragma unroll
        for (int i = 0; i < 4; ++i) {
            int r = r0 + i;
            float inv = 1.0f / sDen[r];
            float2 p0 = unpack2(accS[i][0]);
            float2 p1 = unpack2(accS[i][1]);
            int tg = c * LCH + r;
            *reinterpret_cast<float4*>(g_attn + ((size_t)tg * NB + n) * EMB + h * HID + m0) =
                make_float4(p0.x * inv, p0.y * inv, p1.x * inv, p1.y * inv);
        }
    }
}

// ---------------------------------------------------------------------------
// Kernel D v4: out = attn @ W^T + b via mma.sync bf16x3 split
// grid (16,8) = 128 CTAs, 256 thr (8 warps 2x4), tile M128 x N64, K chunk 64
// smem rows padded to 72 bf16 (144 B -> 16B skew/row, LDSM conflict-free)
// ---------------------------------------------------------------------------
#define ROWB 144                      // bytes per staged row (72 bf16)
#define OAH  0
#define OAL  (OAH + 128 * ROWB)       // 18432
#define OBH  (OAL + 128 * ROWB)       // 36864
#define OBL  (OBH + 64 * ROWB)        // 46080
#define SM_HMMA (OBL + 64 * ROWB)     // 55296 B

__global__ __launch_bounds__(256) void outproj_hmma_kernel(const float* __restrict__ W,
                                                           const float* __restrict__ bias,
                                                           float* __restrict__ out) {
    extern __shared__ char smc[];
    const uint32_t sbase = smem_u32(smc);
    const int tid = threadIdx.x;
    const int wid = tid >> 5, lane = tid & 31;
    const int rb = blockIdx.x * 128;
    const int nb = blockIdx.y * 64;
    const int wr = wid >> 2;          // 0..1 -> M half (64 rows)
    const int wc = wid & 3;           // 0..3 -> N quarter (16 cols)

    float acc[4][2][4];
#pragma unroll
    for (int mt = 0; mt < 4; ++mt)
#pragma unroll
        for (int nt = 0; nt < 2; ++nt)
#pragma unroll
            for (int e = 0; e < 4; ++e) acc[mt][nt][e] = 0.f;

    const float4* Ag = reinterpret_cast<const float4*>(g_attn);
    const float4* Wg = reinterpret_cast<const float4*>(W);

    // ldmatrix source addresses (fixed per thread, koff varies by k-step)
    const int arow = (lane & 15);                 // + m-tile base
    const int akh  = (lane >> 4) * 8;             // k half within 16
    const int brow = (lane & 7);                  // + n-tile base
    const int bkh  = ((lane >> 3) & 1) * 8;

    for (int kc = 0; kc < 8; ++kc) {
        // stage A chunk: 128 rows x 64 k (16 float4 per row)
        for (int i = tid; i < 2048; i += 256) {
            int r = i >> 4, g = i & 15;
            float4 x = Ag[(size_t)(rb + r) * 128 + kc * 16 + g];
            uint32_t h0, h1, l0, l1;
            split4(x, h0, h1, l0, l1);
            char* ph = smc + OAH + r * ROWB + g * 8;
            char* pl = smc + OAL + r * ROWB + g * 8;
            *reinterpret_cast<uint2*>(ph) = make_uint2(h0, h1);
            *reinterpret_cast<uint2*>(pl) = make_uint2(l0, l1);
        }
        // stage B chunk: 64 rows x 64 k
        for (int i = tid; i < 1024; i += 256) {
            int n = i >> 4, g = i & 15;
            float4 x = Wg[(size_t)(nb + n) * 128 + kc * 16 + g];
            uint32_t h0, h1, l0, l1;
            split4(x, h0, h1, l0, l1);
            char* ph = smc + OBH + n * ROWB + g * 8;
            char* pl = smc + OBL + n * ROWB + g * 8;
            *reinterpret_cast<uint2*>(ph) = make_uint2(h0, h1);
            *reinterpret_cast<uint2*>(pl) = make_uint2(l0, l1);
        }
        __syncthreads();

#pragma unroll
        for (int ks = 0; ks < 4; ++ks) {
            const int kb = ks * 16;   // bf16 index within the 64-k chunk
            uint32_t bh[2][2], bl[2][2];
#pragma unroll
            for (int nt = 0; nt < 2; ++nt) {
                int n0 = wc * 16 + nt * 8;
                uint32_t ab = sbase + OBH + (n0 + brow) * ROWB + (kb + bkh) * 2;
                ldsm_x2(bh[nt][0], bh[nt][1], ab);
                uint32_t al = sbase + OBL + (n0 + brow) * ROWB + (kb + bkh) * 2;
                ldsm_x2(bl[nt][0], bl[nt][1], al);
            }
            uint32_t ah[4][4], alr[4][4];
#pragma unroll
            for (int mt = 0; mt < 4; ++mt) {
                int m0 = wr * 64 + mt * 16;
                uint32_t aa = sbase + OAH + (m0 + arow) * ROWB + (kb + akh) * 2;
                ldsm_x4(ah[mt][0], ah[mt][1], ah[mt][2], ah[mt][3], aa);
                uint32_t al2 = sbase + OAL + (m0 + arow) * ROWB + (kb + akh) * 2;
                ldsm_x4(alr[mt][0], alr[mt][1], alr[mt][2], alr[mt][3], al2);
            }
#pragma unroll
            for (int mt = 0; mt < 4; ++mt)
#pragma unroll
                for (int nt = 0; nt < 2; ++nt) {
                    mma_bf16(acc[mt][nt], ah[mt],  bh[nt]);
                    mma_bf16(acc[mt][nt], ah[mt],  bl[nt]);
                    mma_bf16(acc[mt][nt], alr[mt], bh[nt]);
                }
        }
        __syncthreads();
    }

    // epilogue: thread (lane) holds D[gr][gc],D[gr][gc+1],D[gr+8][gc],D[gr+8][gc+1]
    const int gr = lane >> 2, gc = (lane & 3) * 2;
    const int h = blockIdx.y;          // nb = h*64
#pragma unroll
    for (int mt = 0; mt < 4; ++mt) {
#pragma unroll
        for (int nt = 0; nt < 2; ++nt) {
            int d = wc * 16 + nt * 8 + gc;
            float b0 = bias[nb + d], b1 = bias[nb + d + 1];
#pragma unroll
            for (int half = 0; half < 2; ++half) {
                int r = rb + wr * 64 + mt * 16 + gr + half * 8;
                int t = r >> 1, n = r & 1;
                size_t oidx = (((size_t)(n * HH + h) * TT) + t) * HID + d;
                *reinterpret_cast<float2*>(out + oidx) =
                    make_float2(acc[mt][nt][half * 2 + 0] + b0,
                                acc[mt][nt][half * 2 + 1] + b1);
            }
        }
    }
}

// ---------------------------------------------------------------------------
// Launch
// ---------------------------------------------------------------------------
extern "C" void kernel_launch(void* const* d_in, const int* in_sizes, int n_in,
                              void* d_out, int out_size) {
    const float* q    = (const float*)d_in[0];
    const float* k    = (const float*)d_in[1];
    const float* v    = (const float*)d_in[2];
    const float* W    = (const float*)d_in[3];
    const float* bias = (const float*)d_in[4];
    float* out = (float*)d_out;

    static cudaStream_t s_side = nullptr;
    static cudaEvent_t evF = nullptr, evJ = nullptr;
    if (!s_side) {
        cudaStreamCreateWithFlags(&s_side, cudaStreamNonBlocking);
        cudaEventCreateWithFlags(&evF, cudaEventDisableTiming);
        cudaEventCreateWithFlags(&evJ, cudaEventDisableTiming);
    }

    cudaFuncSetAttribute(chunk_out_kernel,
                         cudaFuncAttributeMaxDynamicSharedMemorySize, 67840);
    cudaFuncSetAttribute(outproj_hmma_kernel,
                         cudaFuncAttributeMaxDynamicSharedMemorySize, SM_HMMA);

    const bool has_probs = (out_size > CTX_ELEMS);
    if (has_probs) {
        cudaEventRecord(evF, 0);
        cudaStreamWaitEvent(s_side, evF, 0);
        cudaMemsetAsync(out + CTX_ELEMS, 0,
                        (size_t)(out_size - CTX_ELEMS) * sizeof(float), s_side);
        cudaEventRecord(evJ, s_side);
    }

    chunk_sums_kernel<<<dim3(NHB, NCH), 256, 33280>>>(k, v);
    prefix_kernel<<<dim3(NHB, NCH), 256>>>();
    chunk_out_kernel<<<dim3(NHB, NCH), 256, 67840>>>(q, k, v);
    outproj_hmma_kernel<<<dim3(16, 8), 256, SM_HMMA>>>(W, bias, out);

    if (has_probs) cudaStreamWaitEvent(0, evJ, 0);
}

// round 9
// speedup vs baseline: 1.8422x; 1.8422x over previous
#include <cuda_runtime.h>
#include <cuda_bf16.h>
#include <stdint.h>
#include <math.h>

// Problem constants
#define NB   2
#define HH   8
#define TT   1024
#define HID  64
#define NHB  (NB*HH)
#define D2   (2*HID)
#define EMB  (HH*HID)          // 512
#define LCH  64
#define NCH  (TT/LCH)          // 16
#define CTX_ELEMS (NB*HH*TT*HID)
#define ANG_K 0.0015339807878856412f

typedef unsigned long long u64t;

__device__ __forceinline__ u64t pack2(float lo, float hi) {
    u64t r; asm("mov.b64 %0, {%1, %2};" : "=l"(r) : "f"(lo), "f"(hi)); return r;
}
__device__ __forceinline__ float2 unpack2(u64t p) {
    float2 r; asm("mov.b64 {%0, %1}, %2;" : "=f"(r.x), "=f"(r.y) : "l"(p)); return r;
}
__device__ __forceinline__ void fma2(u64t& d, u64t a, u64t b) {
    asm("fma.rn.f32x2 %0, %1, %2, %0;" : "+l"(d) : "l"(a), "l"(b));
}
__device__ __forceinline__ void mul2(u64t& d, u64t a, u64t b) {
    asm("mul.rn.f32x2 %0, %1, %2;" : "=l"(d) : "l"(a), "l"(b));
}
__device__ __forceinline__ uint32_t smem_u32(const void* p) {
    uint32_t a;
    asm("{ .reg .u64 t; cvta.to.shared.u64 t, %1; cvt.u32.u64 %0, t; }" : "=r"(a) : "l"(p));
    return a;
}

// ---- sm_80-class warp MMA helpers (base PTX; verified correct in R8) ----
__device__ __forceinline__ void ldsm_x4(uint32_t& r0, uint32_t& r1, uint32_t& r2, uint32_t& r3,
                                        uint32_t addr) {
    asm volatile("ldmatrix.sync.aligned.m8n8.x4.shared.b16 {%0,%1,%2,%3}, [%4];"
                 : "=r"(r0), "=r"(r1), "=r"(r2), "=r"(r3) : "r"(addr));
}
__device__ __forceinline__ void mma_bf16(float* c, const uint32_t* a, const uint32_t* b) {
    asm volatile("mma.sync.aligned.m16n8k16.row.col.f32.bf16.bf16.f32 "
                 "{%0,%1,%2,%3}, {%4,%5,%6,%7}, {%8,%9}, {%0,%1,%2,%3};"
                 : "+f"(c[0]), "+f"(c[1]), "+f"(c[2]), "+f"(c[3])
                 : "r"(a[0]), "r"(a[1]), "r"(a[2]), "r"(a[3]), "r"(b[0]), "r"(b[1]));
}
// split fp32 quad -> bf16 hi + bf16 residual, packed bf16x2
__device__ __forceinline__ void split4(float4 x, uint32_t& h0, uint32_t& h1,
                                       uint32_t& l0, uint32_t& l1) {
    __nv_bfloat16 a = __float2bfloat16(x.x), b = __float2bfloat16(x.y),
                  c = __float2bfloat16(x.z), d = __float2bfloat16(x.w);
    __nv_bfloat162 hA(a, b), hB(c, d);
    h0 = *reinterpret_cast<uint32_t*>(&hA);
    h1 = *reinterpret_cast<uint32_t*>(&hB);
    __nv_bfloat162 lA(__float2bfloat16(x.x - __bfloat162float(a)),
                      __float2bfloat16(x.y - __bfloat162float(b)));
    __nv_bfloat162 lB(__float2bfloat16(x.z - __bfloat162float(c)),
                      __float2bfloat16(x.w - __bfloat162float(d)));
    l0 = *reinterpret_cast<uint32_t*>(&lA);
    l1 = *reinterpret_cast<uint32_t*>(&lB);
}

// Scratch (device globals)
__device__ float g_S   [NHB*NCH*D2*HID];
__device__ float g_P   [NHB*NCH*D2*HID];
__device__ float g_sk  [NHB*NCH*D2];
__device__ float g_skP [NHB*NCH*D2];
__device__ __align__(16) __nv_bfloat16 g_attnH[TT*NB*EMB];  // split attn, hi
__device__ __align__(16) __nv_bfloat16 g_attnL[TT*NB*EMB];  // split attn, lo
__device__ __align__(16) __nv_bfloat16 g_WH[EMB*EMB];       // split W, hi
__device__ __align__(16) __nv_bfloat16 g_WL[EMB*EMB];       // split W, lo

// ---------------------------------------------------------------------------
// Kernel W: split W into bf16 hi/lo (runs first; 1MB read)
// grid 64, block 256; each thread 4 float4
// ---------------------------------------------------------------------------
__global__ __launch_bounds__(256) void wsplit_kernel(const float* __restrict__ W) {
    const int tid = blockIdx.x * 256 + threadIdx.x;   // 16384 threads
    const float4* W4 = reinterpret_cast<const float4*>(W);
#pragma unroll
    for (int j = 0; j < 4; ++j) {
        int idx = j * 16384 + tid;                    // 65536 float4 total
        float4 x = W4[idx];
        uint32_t h0, h1, l0, l1;
        split4(x, h0, h1, l0, l1);
        *reinterpret_cast<uint2*>(&g_WH[idx * 4]) = make_uint2(h0, h1);
        *reinterpret_cast<uint2*>(&g_WL[idx * 4]) = make_uint2(l0, l1);
    }
}

// ---------------------------------------------------------------------------
// Kernel A: per-(b,chunk) sums (unchanged, passing since R5)
// ---------------------------------------------------------------------------
__global__ __launch_bounds__(256) void chunk_sums_kernel(const float* __restrict__ k,
                                                         const float* __restrict__ v) {
    extern __shared__ float sm[];
    float* sK   = sm;
    float* sV   = sm + 4096;
    float* sSin = sm + 8192;
    float* sCos = sm + 8256;
    const int b = blockIdx.x, c = blockIdx.y, tid = threadIdx.x;

    if (tid < LCH) {
        float ang = (float)(c * LCH + tid + 1) * ANG_K;
        sSin[tid] = sinf(ang);
        sCos[tid] = cosf(ang);
    }
    const float4* kg = reinterpret_cast<const float4*>(k + ((size_t)b * TT + c * LCH) * HID);
    float4* sK4w = reinterpret_cast<float4*>(sK);
    for (int i = tid; i < LCH * 16; i += 256) {
        float4 kv = kg[i];
        sK4w[i] = make_float4(fmaxf(kv.x, 0.f), fmaxf(kv.y, 0.f),
                              fmaxf(kv.z, 0.f), fmaxf(kv.w, 0.f));
    }
    const float4* vg = reinterpret_cast<const float4*>(v);
    float4* sV4w = reinterpret_cast<float4*>(sV);
    for (int i = tid; i < LCH * 16; i += 256) {
        int t = i >> 4, c4 = i & 15;
        sV4w[t * 16 + c4] = vg[((size_t)(c * LCH + t) * NHB + b) * 16 + c4];
    }
    __syncthreads();

    const int tx = tid & 15, ty = tid >> 4;
    const int m0 = tx * 4;
    const float* wT = (ty < 8) ? sSin : sCos;
    u64t acc[8][2];
#pragma unroll
    for (int i = 0; i < 8; ++i) { acc[i][0] = pack2(0.f, 0.f); acc[i][1] = pack2(0.f, 0.f); }

    const float4* sK4 = reinterpret_cast<const float4*>(sK);
    const float4* sV4 = reinterpret_cast<const float4*>(sV);
    for (int t = 0; t < LCH; ++t) {
        float4 a0 = sK4[t * 16 + (ty & 7) * 2];
        float4 a1 = sK4[t * 16 + (ty & 7) * 2 + 1];
        float4 bv = sV4[t * 16 + tx];
        float w = wT[t];
        u64t wp = pack2(w, w);
        u64t b01 = pack2(bv.x, bv.y), b23 = pack2(bv.z, bv.w);
        mul2(b01, b01, wp);
        mul2(b23, b23, wp);
        float av[8] = {a0.x, a0.y, a0.z, a0.w, a1.x, a1.y, a1.z, a1.w};
#pragma unroll
        for (int i = 0; i < 8; ++i) {
            u64t ad = pack2(av[i], av[i]);
            fma2(acc[i][0], ad, b01);
            fma2(acc[i][1], ad, b23);
        }
    }
    float* Sout = g_S + (size_t)(b * NCH + c) * (D2 * HID);
#pragma unroll
    for (int i = 0; i < 8; ++i) {
        float2 p0 = unpack2(acc[i][0]);
        float2 p1 = unpack2(acc[i][1]);
        *reinterpret_cast<float4*>(Sout + (ty * 8 + i) * HID + m0) =
            make_float4(p0.x, p0.y, p1.x, p1.y);
    }

    if (tid < D2) {
        int dl = tid & 63;
        const float* wv = (tid < 64) ? sSin : sCos;
        float s = 0.f;
        for (int t = 0; t < LCH; ++t) s += wv[t] * sK[t * HID + dl];
        g_sk[(b * NCH + c) * D2 + tid] = s;
    }
}

// ---------------------------------------------------------------------------
// Kernel B: exclusive prefix (unchanged)
// ---------------------------------------------------------------------------
__global__ __launch_bounds__(256) void prefix_kernel() {
    const int b = blockIdx.x, s = blockIdx.y, tid = threadIdx.x;
    size_t eoff = (size_t)s * 512 + tid * 2;
    float r0 = 0.f, r1 = 0.f;
#pragma unroll
    for (int c = 0; c < NCH; ++c) {
        size_t base = (size_t)(b * NCH + c) * (D2 * HID) + eoff;
        float2 sv = *reinterpret_cast<const float2*>(&g_S[base]);
        *reinterpret_cast<float2*>(&g_P[base]) = make_float2(r0, r1);
        r0 += sv.x; r1 += sv.y;
    }
    if (s == 0 && tid < D2) {
        float run = 0.f;
#pragma unroll
        for (int c = 0; c < NCH; ++c) {
            int idx = (b * NCH + c) * D2 + tid;
            g_skP[idx] = run;
            run += g_sk[idx];
        }
    }
}

// ---------------------------------------------------------------------------
// Kernel C: per-(b,chunk) output; epilogue now writes split-bf16 attn
// ---------------------------------------------------------------------------
__global__ __launch_bounds__(256, 3) void chunk_out_kernel(const float* __restrict__ q,
                                                           const float* __restrict__ k,
                                                           const float* __restrict__ v) {
    extern __shared__ float sm[];
    float* sQ   = sm;
    float* sB   = sm + 4096;
    float* sV   = sm + 8448;
    float* sS   = sm + 12544;
    float* sSin = sm + 16640;
    float* sCos = sm + 16704;
    float* sSkp = sm + 16768;
    float* sDen = sm + 16896;

    const int b = blockIdx.x, c = blockIdx.y, tid = threadIdx.x;
    const int lane = tid & 31, w = tid >> 5;

    if (tid < LCH) {
        float ang = (float)(c * LCH + tid + 1) * ANG_K;
        sSin[tid] = sinf(ang);
        sCos[tid] = cosf(ang);
    }
    if (tid < D2) sSkp[tid] = g_skP[(b * NCH + c) * D2 + tid];

    const float4* qg = reinterpret_cast<const float4*>(q + ((size_t)b * TT + c * LCH) * HID);
    const float4* kg = reinterpret_cast<const float4*>(k + ((size_t)b * TT + c * LCH) * HID);
    float4* sQ4w = reinterpret_cast<float4*>(sQ);
    float4* sB4w = reinterpret_cast<float4*>(sB);
    for (int i = tid; i < LCH * 16; i += 256) {
        int t = i >> 4, c4 = i & 15;
        float4 qv = qg[i];
        sQ4w[i] = make_float4(fmaxf(qv.x, 0.f), fmaxf(qv.y, 0.f),
                              fmaxf(qv.z, 0.f), fmaxf(qv.w, 0.f));
        float4 kv = kg[i];
        sB4w[t * 17 + c4] = make_float4(fmaxf(kv.x, 0.f), fmaxf(kv.y, 0.f),
                                        fmaxf(kv.z, 0.f), fmaxf(kv.w, 0.f));
    }
    const float4* vg = reinterpret_cast<const float4*>(v);
    float4* sV4w = reinterpret_cast<float4*>(sV);
    for (int i = tid; i < LCH * 16; i += 256) {
        int t = i >> 4, c4 = i & 15;
        sV4w[t * 16 + c4] = vg[((size_t)(c * LCH + t) * NHB + b) * 16 + c4];
    }
    __syncthreads();

    {
        const float4* sQ4 = reinterpret_cast<const float4*>(sQ);
        const float4* sK4 = reinterpret_cast<const float4*>(sB);
        const int r0 = w * 8;
        float acc0[8] = {0,0,0,0,0,0,0,0};
        float acc1[8] = {0,0,0,0,0,0,0,0};
        if (w < 4) {
            for (int d4 = 0; d4 < 16; ++d4) {
                float4 k0 = sK4[lane * 17 + d4];
#pragma unroll
                for (int i = 0; i < 8; ++i) {
                    float4 qv = sQ4[(r0 + i) * 16 + d4];
                    acc0[i] = fmaf(qv.x, k0.x, acc0[i]);
                    acc0[i] = fmaf(qv.y, k0.y, acc0[i]);
                    acc0[i] = fmaf(qv.z, k0.z, acc0[i]);
                    acc0[i] = fmaf(qv.w, k0.w, acc0[i]);
                }
            }
        } else {
            for (int d4 = 0; d4 < 16; ++d4) {
                float4 k0 = sK4[lane * 17 + d4];
                float4 k1 = sK4[(lane + 32) * 17 + d4];
#pragma unroll
                for (int i = 0; i < 8; ++i) {
                    float4 qv = sQ4[(r0 + i) * 16 + d4];
                    acc0[i] = fmaf(qv.x, k0.x, acc0[i]);
                    acc0[i] = fmaf(qv.y, k0.y, acc0[i]);
                    acc0[i] = fmaf(qv.z, k0.z, acc0[i]);
                    acc0[i] = fmaf(qv.w, k0.w, acc0[i]);
                    acc1[i] = fmaf(qv.x, k1.x, acc1[i]);
                    acc1[i] = fmaf(qv.y, k1.y, acc1[i]);
                    acc1[i] = fmaf(qv.z, k1.z, acc1[i]);
                    acc1[i] = fmaf(qv.w, k1.w, acc1[i]);
                }
            }
        }
        float sk0 = sSin[lane], ck0 = sCos[lane];
        float sk1 = sSin[lane + 32], ck1 = sCos[lane + 32];
#pragma unroll
        for (int i = 0; i < 8; ++i) {
            int r = r0 + i;
            float sr = sSin[r], cr = sCos[r];
            float f0 = cr * ck0 + sr * sk0;
            float f1 = cr * ck1 + sr * sk1;
            float v0 = (lane <= r)      ? acc0[i] * f0 : 0.f;
            float v1 = (lane + 32 <= r) ? acc1[i] * f1 : 0.f;
            sS[r * LCH + lane]      = v0;
            sS[r * LCH + lane + 32] = v1;
            float qra = sQ[r * HID + lane];
            float qrb = sQ[r * HID + lane + 32];
            float pl = sr * (qra * sSkp[lane] + qrb * sSkp[lane + 32])
                     + cr * (qra * sSkp[64 + lane] + qrb * sSkp[96 + lane]);
            float p = v0 + v1 + pl;
#pragma unroll
            for (int o = 16; o > 0; o >>= 1) p += __shfl_xor_sync(0xFFFFFFFFu, p, o);
            if (lane == 0) sDen[r] = fmaxf(p, 1e-6f);
        }
    }
    __syncthreads();

    {
        const int tx = tid & 15, ty = tid >> 4;
        const int r0 = ty * 4, m0 = tx * 4;
        const float4* sQ4 = reinterpret_cast<const float4*>(sQ);
        const float4* sS4 = reinterpret_cast<const float4*>(sS);
        const float4* sV4 = reinterpret_cast<const float4*>(sV);
        const float4* sP4 = reinterpret_cast<const float4*>(sB);
        const float4* Pg  = reinterpret_cast<const float4*>(
                                g_P + (size_t)(b * NCH + c) * (D2 * HID));
        float4* sPw = reinterpret_cast<float4*>(sB);

        u64t accS[4][2], accT[4][2];
#pragma unroll
        for (int i = 0; i < 4; ++i) { accS[i][0] = pack2(0.f,0.f); accS[i][1] = pack2(0.f,0.f); }

        for (int tp4 = 0; tp4 < 16; ++tp4) {
            float4 a[4];
#pragma unroll
            for (int i = 0; i < 4; ++i) a[i] = sS4[(r0 + i) * 16 + tp4];
            float4 b0 = sV4[(4 * tp4 + 0) * 16 + tx];
            float4 b1 = sV4[(4 * tp4 + 1) * 16 + tx];
            float4 b2 = sV4[(4 * tp4 + 2) * 16 + tx];
            float4 b3 = sV4[(4 * tp4 + 3) * 16 + tx];
            u64t b0l = pack2(b0.x,b0.y), b0h = pack2(b0.z,b0.w);
            u64t b1l = pack2(b1.x,b1.y), b1h = pack2(b1.z,b1.w);
            u64t b2l = pack2(b2.x,b2.y), b2h = pack2(b2.z,b2.w);
            u64t b3l = pack2(b3.x,b3.y), b3h = pack2(b3.z,b3.w);
#pragma unroll
            for (int i = 0; i < 4; ++i) {
                u64t ax = pack2(a[i].x, a[i].x); fma2(accS[i][0], ax, b0l); fma2(accS[i][1], ax, b0h);
                u64t ay = pack2(a[i].y, a[i].y); fma2(accS[i][0], ay, b1l); fma2(accS[i][1], ay, b1h);
                u64t az = pack2(a[i].z, a[i].z); fma2(accS[i][0], az, b2l); fma2(accS[i][1], az, b2h);
                u64t aw = pack2(a[i].w, a[i].w); fma2(accS[i][0], aw, b3l); fma2(accS[i][1], aw, b3h);
            }
        }
        __syncthreads();

#pragma unroll
        for (int half = 0; half < 2; ++half) {
            for (int i = tid; i < 1024; i += 256) {
                int row = i >> 4, c4 = i & 15;
                sPw[row * 17 + c4] = Pg[half * 1024 + i];
            }
            __syncthreads();
#pragma unroll
            for (int i = 0; i < 4; ++i) { accT[i][0] = pack2(0.f,0.f); accT[i][1] = pack2(0.f,0.f); }
            for (int d4 = 0; d4 < 16; ++d4) {
                float4 a[4];
#pragma unroll
                for (int i = 0; i < 4; ++i) a[i] = sQ4[(r0 + i) * 16 + d4];
                float4 b0 = sP4[(4 * d4 + 0) * 17 + tx];
                float4 b1 = sP4[(4 * d4 + 1) * 17 + tx];
                float4 b2 = sP4[(4 * d4 + 2) * 17 + tx];
                float4 b3 = sP4[(4 * d4 + 3) * 17 + tx];
                u64t b0l = pack2(b0.x,b0.y), b0h = pack2(b0.z,b0.w);
                u64t b1l = pack2(b1.x,b1.y), b1h = pack2(b1.z,b1.w);
                u64t b2l = pack2(b2.x,b2.y), b2h = pack2(b2.z,b2.w);
                u64t b3l = pack2(b3.x,b3.y), b3h = pack2(b3.z,b3.w);
#pragma unroll
                for (int i = 0; i < 4; ++i) {
                    u64t ax = pack2(a[i].x, a[i].x); fma2(accT[i][0], ax, b0l); fma2(accT[i][1], ax, b0h);
                    u64t ay = pack2(a[i].y, a[i].y); fma2(accT[i][0], ay, b1l); fma2(accT[i][1], ay, b1h);
                    u64t az = pack2(a[i].z, a[i].z); fma2(accT[i][0], az, b2l); fma2(accT[i][1], az, b2h);
                    u64t aw = pack2(a[i].w, a[i].w); fma2(accT[i][0], aw, b3l); fma2(accT[i][1], aw, b3h);
                }
            }
            const float* wT = half ? sCos : sSin;
#pragma unroll
            for (int i = 0; i < 4; ++i) {
                float wv = wT[r0 + i];
                u64t wd = pack2(wv, wv);
                fma2(accS[i][0], wd, accT[i][0]);
                fma2(accS[i][1], wd, accT[i][1]);
            }
            if (half == 0) __syncthreads();
        }

        const int n = b >> 3, h = b & 7;
#pragma unroll
        for (int i = 0; i < 4; ++i) {
            int r = r0 + i;
            float inv = 1.0f / sDen[r];
            float2 p0 = unpack2(accS[i][0]);
            float2 p1 = unpack2(accS[i][1]);
            int tg = c * LCH + r;
            size_t base = ((size_t)tg * NB + n) * EMB + h * HID + m0;
            uint32_t h0, h1, l0, l1;
            split4(make_float4(p0.x * inv, p0.y * inv, p1.x * inv, p1.y * inv),
                   h0, h1, l0, l1);
            *reinterpret_cast<uint2*>(&g_attnH[base]) = make_uint2(h0, h1);
            *reinterpret_cast<uint2*>(&g_attnL[base]) = make_uint2(l0, l1);
        }
    }
}

// ---------------------------------------------------------------------------
// Kernel D v5: out = attn @ W^T + b via mma.sync bf16x3 (pre-split operands)
// grid (32,8) = 256 CTAs, 128 thr (4 warps, warp = 16 rows x 64 cols)
// M tile 64, N tile 64, K chunk 128. smem 68 KB -> 2 CTAs/SM.
// Row stride 272 B (16B skew/row -> ldmatrix conflict-free).
// ---------------------------------------------------------------------------
#define ROWB 272
#define OAH  0
#define OAL  (OAH + 64 * ROWB)    // 17408
#define OBH  (OAL + 64 * ROWB)    // 34816
#define OBL  (OBH + 64 * ROWB)    // 52224
#define SM_HMMA (OBL + 64 * ROWB) // 69632

__global__ __launch_bounds__(128) void outproj_hmma_kernel(const float* __restrict__ bias,
                                                           float* __restrict__ out) {
    extern __shared__ char smc[];
    const uint32_t sbase = smem_u32(smc);
    const int tid = threadIdx.x;
    const int wid = tid >> 5, lane = tid & 31;
    const int rb = blockIdx.x * 64;    // attn row base
    const int nb = blockIdx.y * 64;    // out col base
    const int wm0 = wid * 16;          // warp's row offset within tile

    float acc[8][4];
#pragma unroll
    for (int nt = 0; nt < 8; ++nt)
#pragma unroll
        for (int e = 0; e < 4; ++e) acc[nt][e] = 0.f;

    // ldmatrix per-lane addresses (k offset added per step)
    const uint32_t aAddr = sbase + OAH + (wm0 + (lane & 15)) * ROWB + ((lane >> 4) * 8) * 2;
    const uint32_t aAddrL = aAddr + (OAL - OAH);
    const int brow = (lane & 7) + ((lane >> 4) << 3);   // covers n16 via x4
    const int bkh  = ((lane >> 3) & 1) * 8;
    const uint32_t bAddr  = sbase + OBH + brow * ROWB + bkh * 2;
    const uint32_t bAddrL = bAddr + (OBL - OBH);

    for (int kc = 0; kc < 4; ++kc) {
        // stage: pure coalesced uint4 copies of pre-split bf16 (no math)
        const size_t kbase = (size_t)kc * 128;
        for (int i = tid; i < 1024; i += 128) {
            int r = i >> 4, g = i & 15;   // 64 rows x 16 uint4 (128 bf16)
            const uint4* aH = reinterpret_cast<const uint4*>(&g_attnH[(size_t)(rb + r) * EMB + kbase]);
            const uint4* aL = reinterpret_cast<const uint4*>(&g_attnL[(size_t)(rb + r) * EMB + kbase]);
            const uint4* bH = reinterpret_cast<const uint4*>(&g_WH[(size_t)(nb + r) * EMB + kbase]);
            const uint4* bL = reinterpret_cast<const uint4*>(&g_WL[(size_t)(nb + r) * EMB + kbase]);
            char* dst = smc + r * ROWB + g * 16;
            *reinterpret_cast<uint4*>(dst + OAH) = aH[g];
            *reinterpret_cast<uint4*>(dst + OAL) = aL[g];
            *reinterpret_cast<uint4*>(dst + OBH) = bH[g];
            *reinterpret_cast<uint4*>(dst + OBL) = bL[g];
        }
        __syncthreads();

#pragma unroll
        for (int ks = 0; ks < 8; ++ks) {
            const int ko = ks * 32;   // 16 bf16 * 2 bytes
            uint32_t ah[4], al[4];
            ldsm_x4(ah[0], ah[1], ah[2], ah[3], aAddr + ko);
            ldsm_x4(al[0], al[1], al[2], al[3], aAddrL + ko);
            uint32_t bh[8][2], bl[8][2];
#pragma unroll
            for (int p = 0; p < 4; ++p) {   // each x4 covers n16 (2 tiles)
                ldsm_x4(bh[2*p][0], bh[2*p][1], bh[2*p+1][0], bh[2*p+1][1],
                        bAddr + p * 16 * ROWB + ko);
                ldsm_x4(bl[2*p][0], bl[2*p][1], bl[2*p+1][0], bl[2*p+1][1],
                        bAddrL + p * 16 * ROWB + ko);
            }
#pragma unroll
            for (int nt = 0; nt < 8; ++nt) {
                mma_bf16(acc[nt], ah, bh[nt]);
                mma_bf16(acc[nt], ah, bl[nt]);
                mma_bf16(acc[nt], al, bh[nt]);
            }
        }
        __syncthreads();
    }

    // epilogue: lane holds D[gr][gc], D[gr][gc+1], D[gr+8][gc], D[gr+8][gc+1]
    const int gr = lane >> 2, gc = (lane & 3) * 2;
    const int h = blockIdx.y;
#pragma unroll
    for (int nt = 0; nt < 8; ++nt) {
        int d = nt * 8 + gc;
        float b0 = bias[nb + d], b1 = bias[nb + d + 1];
#pragma unroll
        for (int half = 0; half < 2; ++half) {
            int r = rb + wm0 + gr + half * 8;
            int t = r >> 1, n = r & 1;
            size_t oidx = (((size_t)(n * HH + h) * TT) + t) * HID + d;
            *reinterpret_cast<float2*>(out + oidx) =
                make_float2(acc[nt][half * 2 + 0] + b0,
                            acc[nt][half * 2 + 1] + b1);
        }
    }
}

// ---------------------------------------------------------------------------
// Launch
// ---------------------------------------------------------------------------
extern "C" void kernel_launch(void* const* d_in, const int* in_sizes, int n_in,
                              void* d_out, int out_size) {
    const float* q    = (const float*)d_in[0];
    const float* k    = (const float*)d_in[1];
    const float* v    = (const float*)d_in[2];
    const float* W    = (const float*)d_in[3];
    const float* bias = (const float*)d_in[4];
    float* out = (float*)d_out;

    static cudaStream_t s_side = nullptr;
    static cudaEvent_t evF = nullptr, evJ = nullptr;
    if (!s_side) {
        cudaStreamCreateWithFlags(&s_side, cudaStreamNonBlocking);
        cudaEventCreateWithFlags(&evF, cudaEventDisableTiming);
        cudaEventCreateWithFlags(&evJ, cudaEventDisableTiming);
    }

    cudaFuncSetAttribute(chunk_out_kernel,
                         cudaFuncAttributeMaxDynamicSharedMemorySize, 67840);
    cudaFuncSetAttribute(outproj_hmma_kernel,
                         cudaFuncAttributeMaxDynamicSharedMemorySize, SM_HMMA);

    const bool has_probs = (out_size > CTX_ELEMS);
    if (has_probs) {
        cudaEventRecord(evF, 0);
        cudaStreamWaitEvent(s_side, evF, 0);
        cudaMemsetAsync(out + CTX_ELEMS, 0,
                        (size_t)(out_size - CTX_ELEMS) * sizeof(float), s_side);
        cudaEventRecord(evJ, s_side);
    }

    wsplit_kernel<<<64, 256>>>(W);
    chunk_sums_kernel<<<dim3(NHB, NCH), 256, 33280>>>(k, v);
    prefix_kernel<<<dim3(NHB, NCH), 256>>>();
    chunk_out_kernel<<<dim3(NHB, NCH), 256, 67840>>>(q, k, v);
    outproj_hmma_kernel<<<dim3(32, 8), 128, SM_HMMA>>>(bias, out);

    if (has_probs) cudaStreamWaitEvent(0, evJ, 0);
}

// round 10
// speedup vs baseline: 1.8920x; 1.0270x over previous
#include <cuda_runtime.h>
#include <cuda_bf16.h>
#include <stdint.h>
#include <math.h>

// Problem constants
#define NB   2
#define HH   8
#define TT   1024
#define HID  64
#define NHB  (NB*HH)
#define D2   (2*HID)
#define EMB  (HH*HID)          // 512
#define LCH  64
#define NCH  (TT/LCH)          // 16
#define CTX_ELEMS (NB*HH*TT*HID)
#define ANG_K 0.0015339807878856412f

typedef unsigned long long u64t;

__device__ __forceinline__ u64t pack2(float lo, float hi) {
    u64t r; asm("mov.b64 %0, {%1, %2};" : "=l"(r) : "f"(lo), "f"(hi)); return r;
}
__device__ __forceinline__ float2 unpack2(u64t p) {
    float2 r; asm("mov.b64 {%0, %1}, %2;" : "=f"(r.x), "=f"(r.y) : "l"(p)); return r;
}
__device__ __forceinline__ void fma2(u64t& d, u64t a, u64t b) {
    asm("fma.rn.f32x2 %0, %1, %2, %0;" : "+l"(d) : "l"(a), "l"(b));
}
__device__ __forceinline__ void mul2(u64t& d, u64t a, u64t b) {
    asm("mul.rn.f32x2 %0, %1, %2;" : "=l"(d) : "l"(a), "l"(b));
}
__device__ __forceinline__ uint32_t smem_u32(const void* p) {
    uint32_t a;
    asm("{ .reg .u64 t; cvta.to.shared.u64 t, %1; cvt.u32.u64 %0, t; }" : "=r"(a) : "l"(p));
    return a;
}

// ---- sm_80-class warp MMA helpers (verified R8/R9) ----
__device__ __forceinline__ void ldsm_x4(uint32_t& r0, uint32_t& r1, uint32_t& r2, uint32_t& r3,
                                        uint32_t addr) {
    asm volatile("ldmatrix.sync.aligned.m8n8.x4.shared.b16 {%0,%1,%2,%3}, [%4];"
                 : "=r"(r0), "=r"(r1), "=r"(r2), "=r"(r3) : "r"(addr));
}
__device__ __forceinline__ void mma_bf16(float* c, const uint32_t* a, const uint32_t* b) {
    asm volatile("mma.sync.aligned.m16n8k16.row.col.f32.bf16.bf16.f32 "
                 "{%0,%1,%2,%3}, {%4,%5,%6,%7}, {%8,%9}, {%0,%1,%2,%3};"
                 : "+f"(c[0]), "+f"(c[1]), "+f"(c[2]), "+f"(c[3])
                 : "r"(a[0]), "r"(a[1]), "r"(a[2]), "r"(a[3]), "r"(b[0]), "r"(b[1]));
}
__device__ __forceinline__ void split4(float4 x, uint32_t& h0, uint32_t& h1,
                                       uint32_t& l0, uint32_t& l1) {
    __nv_bfloat16 a = __float2bfloat16(x.x), b = __float2bfloat16(x.y),
                  c = __float2bfloat16(x.z), d = __float2bfloat16(x.w);
    __nv_bfloat162 hA(a, b), hB(c, d);
    h0 = *reinterpret_cast<uint32_t*>(&hA);
    h1 = *reinterpret_cast<uint32_t*>(&hB);
    __nv_bfloat162 lA(__float2bfloat16(x.x - __bfloat162float(a)),
                      __float2bfloat16(x.y - __bfloat162float(b)));
    __nv_bfloat162 lB(__float2bfloat16(x.z - __bfloat162float(c)),
                      __float2bfloat16(x.w - __bfloat162float(d)));
    l0 = *reinterpret_cast<uint32_t*>(&lA);
    l1 = *reinterpret_cast<uint32_t*>(&lB);
}
__device__ __forceinline__ void split2(float v0, float v1, uint32_t& hp, uint32_t& lp) {
    __nv_bfloat16 h0 = __float2bfloat16(v0), h1 = __float2bfloat16(v1);
    __nv_bfloat162 hv(h0, h1);
    hp = *reinterpret_cast<uint32_t*>(&hv);
    __nv_bfloat162 lv(__float2bfloat16(v0 - __bfloat162float(h0)),
                      __float2bfloat16(v1 - __bfloat162float(h1)));
    lp = *reinterpret_cast<uint32_t*>(&lv);
}
__device__ __forceinline__ void splitS(float v, __nv_bfloat16& h, __nv_bfloat16& l) {
    h = __float2bfloat16(v);
    l = __float2bfloat16(v - __bfloat162float(h));
}

// Scratch (device globals)
__device__ float g_S   [NHB*NCH*D2*HID];
__device__ float g_P   [NHB*NCH*D2*HID];
__device__ float g_sk  [NHB*NCH*D2];
__device__ float g_skP [NHB*NCH*D2];
__device__ __align__(16) __nv_bfloat16 g_attnH[TT*NB*EMB];
__device__ __align__(16) __nv_bfloat16 g_attnL[TT*NB*EMB];
__device__ __align__(16) __nv_bfloat16 g_WH[EMB*EMB];
__device__ __align__(16) __nv_bfloat16 g_WL[EMB*EMB];

// ---------------------------------------------------------------------------
// Kernel W: split W into bf16 hi/lo (unchanged, passing)
// ---------------------------------------------------------------------------
__global__ __launch_bounds__(256) void wsplit_kernel(const float* __restrict__ W) {
    const int tid = blockIdx.x * 256 + threadIdx.x;
    const float4* W4 = reinterpret_cast<const float4*>(W);
#pragma unroll
    for (int j = 0; j < 4; ++j) {
        int idx = j * 16384 + tid;
        float4 x = W4[idx];
        uint32_t h0, h1, l0, l1;
        split4(x, h0, h1, l0, l1);
        *reinterpret_cast<uint2*>(&g_WH[idx * 4]) = make_uint2(h0, h1);
        *reinterpret_cast<uint2*>(&g_WL[idx * 4]) = make_uint2(l0, l1);
    }
}

// ---------------------------------------------------------------------------
// Kernel A: per-(b,chunk) sums (unchanged, passing)
// ---------------------------------------------------------------------------
__global__ __launch_bounds__(256) void chunk_sums_kernel(const float* __restrict__ k,
                                                         const float* __restrict__ v) {
    extern __shared__ float sm[];
    float* sK   = sm;
    float* sV   = sm + 4096;
    float* sSin = sm + 8192;
    float* sCos = sm + 8256;
    const int b = blockIdx.x, c = blockIdx.y, tid = threadIdx.x;

    if (tid < LCH) {
        float ang = (float)(c * LCH + tid + 1) * ANG_K;
        sSin[tid] = sinf(ang);
        sCos[tid] = cosf(ang);
    }
    const float4* kg = reinterpret_cast<const float4*>(k + ((size_t)b * TT + c * LCH) * HID);
    float4* sK4w = reinterpret_cast<float4*>(sK);
    for (int i = tid; i < LCH * 16; i += 256) {
        float4 kv = kg[i];
        sK4w[i] = make_float4(fmaxf(kv.x, 0.f), fmaxf(kv.y, 0.f),
                              fmaxf(kv.z, 0.f), fmaxf(kv.w, 0.f));
    }
    const float4* vg = reinterpret_cast<const float4*>(v);
    float4* sV4w = reinterpret_cast<float4*>(sV);
    for (int i = tid; i < LCH * 16; i += 256) {
        int t = i >> 4, c4 = i & 15;
        sV4w[t * 16 + c4] = vg[((size_t)(c * LCH + t) * NHB + b) * 16 + c4];
    }
    __syncthreads();

    const int tx = tid & 15, ty = tid >> 4;
    const int m0 = tx * 4;
    const float* wT = (ty < 8) ? sSin : sCos;
    u64t acc[8][2];
#pragma unroll
    for (int i = 0; i < 8; ++i) { acc[i][0] = pack2(0.f, 0.f); acc[i][1] = pack2(0.f, 0.f); }

    const float4* sK4 = reinterpret_cast<const float4*>(sK);
    const float4* sV4 = reinterpret_cast<const float4*>(sV);
    for (int t = 0; t < LCH; ++t) {
        float4 a0 = sK4[t * 16 + (ty & 7) * 2];
        float4 a1 = sK4[t * 16 + (ty & 7) * 2 + 1];
        float4 bv = sV4[t * 16 + tx];
        float w = wT[t];
        u64t wp = pack2(w, w);
        u64t b01 = pack2(bv.x, bv.y), b23 = pack2(bv.z, bv.w);
        mul2(b01, b01, wp);
        mul2(b23, b23, wp);
        float av[8] = {a0.x, a0.y, a0.z, a0.w, a1.x, a1.y, a1.z, a1.w};
#pragma unroll
        for (int i = 0; i < 8; ++i) {
            u64t ad = pack2(av[i], av[i]);
            fma2(acc[i][0], ad, b01);
            fma2(acc[i][1], ad, b23);
        }
    }
    float* Sout = g_S + (size_t)(b * NCH + c) * (D2 * HID);
#pragma unroll
    for (int i = 0; i < 8; ++i) {
        float2 p0 = unpack2(acc[i][0]);
        float2 p1 = unpack2(acc[i][1]);
        *reinterpret_cast<float4*>(Sout + (ty * 8 + i) * HID + m0) =
            make_float4(p0.x, p0.y, p1.x, p1.y);
    }

    if (tid < D2) {
        int dl = tid & 63;
        const float* wv = (tid < 64) ? sSin : sCos;
        float s = 0.f;
        for (int t = 0; t < LCH; ++t) s += wv[t] * sK[t * HID + dl];
        g_sk[(b * NCH + c) * D2 + tid] = s;
    }
}

// ---------------------------------------------------------------------------
// Kernel B: exclusive prefix (unchanged)
// ---------------------------------------------------------------------------
__global__ __launch_bounds__(256) void prefix_kernel() {
    const int b = blockIdx.x, s = blockIdx.y, tid = threadIdx.x;
    size_t eoff = (size_t)s * 512 + tid * 2;
    float r0 = 0.f, r1 = 0.f;
#pragma unroll
    for (int c = 0; c < NCH; ++c) {
        size_t base = (size_t)(b * NCH + c) * (D2 * HID) + eoff;
        float2 sv = *reinterpret_cast<const float2*>(&g_S[base]);
        *reinterpret_cast<float2*>(&g_P[base]) = make_float2(r0, r1);
        r0 += sv.x; r1 += sv.y;
    }
    if (s == 0 && tid < D2) {
        float run = 0.f;
#pragma unroll
        for (int c = 0; c < NCH; ++c) {
            int idx = (b * NCH + c) * D2 + tid;
            g_skP[idx] = run;
            run += g_sk[idx];
        }
    }
}

// ---------------------------------------------------------------------------
// Kernel C v2: per-(b,chunk) output via mma.sync bf16x3
// grid (16,16), 128 thr (4 warps x 16 rows). smem 56320 B -> 3 CTAs/SM.
// Phases: stage -> score mma (causal skip) + denom -> S frags -> S@V ->
//         P half0/half1 (stage+mma) -> epilogue split-bf16 attn.
// ---------------------------------------------------------------------------
#define ROW2 144                 // 72 bf16 per row, 16B-aligned rows
#define CW_QH 0
#define CW_QL 9216
#define CW_SH 18432              // K, then S
#define CW_SL 27648
#define CW_PH 36864              // V^T, then P^T halves
#define CW_PL 46080
#define CW_FLT 55296             // sin[64] cos[64] skp[128]
#define SM_CO (CW_FLT + 1024)

__global__ __launch_bounds__(128, 3) void chunk_out_hmma(const float* __restrict__ q,
                                                         const float* __restrict__ k,
                                                         const float* __restrict__ v) {
    extern __shared__ char smc[];
    const uint32_t sbase = smem_u32(smc);
    const int tid = threadIdx.x;
    const int wid = tid >> 5, lane = tid & 31;
    const int b = blockIdx.x, c = blockIdx.y;
    const int wm0 = wid * 16;

    float* sF = reinterpret_cast<float*>(smc + CW_FLT);   // sin|cos|skp
    if (tid < 64) {
        float ang = (float)(c * LCH + tid + 1) * ANG_K;
        sF[tid] = sinf(ang);
        sF[64 + tid] = cosf(ang);
    }
    if (tid < 128) sF[128 + tid] = g_skP[(b * NCH + c) * D2 + tid];

    // ---- stage Q, K (relu, split) ----
    const float4* qg = reinterpret_cast<const float4*>(q + ((size_t)b * TT + c * LCH) * HID);
    const float4* kg = reinterpret_cast<const float4*>(k + ((size_t)b * TT + c * LCH) * HID);
    for (int i = tid; i < 1024; i += 128) {
        int t = i >> 4, c4 = i & 15;
        float4 qv = qg[i];
        qv = make_float4(fmaxf(qv.x, 0.f), fmaxf(qv.y, 0.f), fmaxf(qv.z, 0.f), fmaxf(qv.w, 0.f));
        uint32_t h0, h1, l0, l1;
        split4(qv, h0, h1, l0, l1);
        *reinterpret_cast<uint2*>(smc + CW_QH + t * ROW2 + c4 * 8) = make_uint2(h0, h1);
        *reinterpret_cast<uint2*>(smc + CW_QL + t * ROW2 + c4 * 8) = make_uint2(l0, l1);
        float4 kv = kg[i];
        kv = make_float4(fmaxf(kv.x, 0.f), fmaxf(kv.y, 0.f), fmaxf(kv.z, 0.f), fmaxf(kv.w, 0.f));
        split4(kv, h0, h1, l0, l1);
        *reinterpret_cast<uint2*>(smc + CW_SH + t * ROW2 + c4 * 8) = make_uint2(h0, h1);
        *reinterpret_cast<uint2*>(smc + CW_SL + t * ROW2 + c4 * 8) = make_uint2(l0, l1);
    }
    // ---- stage V^T (split, transposed) ----
    {
        const float4* vg = reinterpret_cast<const float4*>(v);
        __nv_bfloat16* vh = reinterpret_cast<__nv_bfloat16*>(smc + CW_PH);
        __nv_bfloat16* vl = reinterpret_cast<__nv_bfloat16*>(smc + CW_PL);
        for (int i = tid; i < 1024; i += 128) {
            int tp = i >> 4, mq = i & 15;
            float4 x = vg[((size_t)(c * LCH + tp) * NHB + b) * 16 + mq];
            float xv[4] = {x.x, x.y, x.z, x.w};
#pragma unroll
            for (int e = 0; e < 4; ++e) {
                __nv_bfloat16 h, l;
                splitS(xv[e], h, l);
                vh[(4 * mq + e) * 72 + tp] = h;
                vl[(4 * mq + e) * 72 + tp] = l;
            }
        }
    }
    __syncthreads();

    // fragment address bases (R9-verified patterns)
    const uint32_t aOffQ = (uint32_t)((wm0 + (lane & 15)) * ROW2 + ((lane >> 4) * 8) * 2);
    const uint32_t bOff  = (uint32_t)(((lane & 7) + ((lane >> 4) << 3)) * ROW2 +
                                      (((lane >> 3) & 1) * 8) * 2);

    // ---- score: acc = Q K^T (bf16x3), causal pair-skip ----
    float acc[8][4];
#pragma unroll
    for (int nt = 0; nt < 8; ++nt)
#pragma unroll
        for (int e = 0; e < 4; ++e) acc[nt][e] = 0.f;
    {
        const int pmax = wid + 1;
        for (int ks = 0; ks < 4; ++ks) {
            const int ko = ks * 32;
            uint32_t ah[4], al[4];
            ldsm_x4(ah[0], ah[1], ah[2], ah[3], sbase + CW_QH + aOffQ + ko);
            ldsm_x4(al[0], al[1], al[2], al[3], sbase + CW_QL + aOffQ + ko);
            for (int p = 0; p < pmax; ++p) {
                uint32_t bh[4], bl[4];
                ldsm_x4(bh[0], bh[1], bh[2], bh[3],
                        sbase + CW_SH + bOff + p * 16 * ROW2 + ko);
                ldsm_x4(bl[0], bl[1], bl[2], bl[3],
                        sbase + CW_SL + bOff + p * 16 * ROW2 + ko);
                mma_bf16(acc[2*p],   ah, bh);     mma_bf16(acc[2*p],   ah, bl);
                mma_bf16(acc[2*p],   al, bh);
                mma_bf16(acc[2*p+1], ah, bh + 2); mma_bf16(acc[2*p+1], ah, bl + 2);
                mma_bf16(acc[2*p+1], al, bh + 2);
            }
        }
    }

    // ---- factor + mask + denominator ----
    const int gr = lane >> 2, gc = (lane & 3) * 2;
    const int r0 = wm0 + gr, r1 = r0 + 8;
    const float sr0 = sF[r0], cr0 = sF[64 + r0];
    const float sr1 = sF[r1], cr1 = sF[64 + r1];
    float rs0 = 0.f, rs1 = 0.f;
#pragma unroll
    for (int nt = 0; nt < 8; ++nt) {
        int c0 = nt * 8 + gc, c1 = c0 + 1;
        float sc0 = sF[c0], cc0 = sF[64 + c0], sc1 = sF[c1], cc1 = sF[64 + c1];
        acc[nt][0] = (c0 <= r0) ? acc[nt][0] * (cr0 * cc0 + sr0 * sc0) : 0.f;
        acc[nt][1] = (c1 <= r0) ? acc[nt][1] * (cr0 * cc1 + sr0 * sc1) : 0.f;
        acc[nt][2] = (c0 <= r1) ? acc[nt][2] * (cr1 * cc0 + sr1 * sc0) : 0.f;
        acc[nt][3] = (c1 <= r1) ? acc[nt][3] * (cr1 * cc1 + sr1 * sc1) : 0.f;
        rs0 += acc[nt][0] + acc[nt][1];
        rs1 += acc[nt][2] + acc[nt][3];
    }
    rs0 += __shfl_xor_sync(0xFFFFFFFFu, rs0, 1); rs0 += __shfl_xor_sync(0xFFFFFFFFu, rs0, 2);
    rs1 += __shfl_xor_sync(0xFFFFFFFFu, rs1, 1); rs1 += __shfl_xor_sync(0xFFFFFFFFu, rs1, 2);
    // qd = q_ . skP for rows r0, r1 (reconstruct q from hi+lo)
    float qd0 = 0.f, qd1 = 0.f;
    {
        const __nv_bfloat16* qh = reinterpret_cast<const __nv_bfloat16*>(smc + CW_QH);
        const __nv_bfloat16* ql = reinterpret_cast<const __nv_bfloat16*>(smc + CW_QL);
        const int d0 = (lane & 3) * 16;
#pragma unroll
        for (int j = 0; j < 16; ++j) {
            int dl = d0 + j;
            float w0 = sr0 * sF[128 + dl] + cr0 * sF[192 + dl];
            float w1 = sr1 * sF[128 + dl] + cr1 * sF[192 + dl];
            float q0 = __bfloat162float(qh[r0 * 72 + dl]) + __bfloat162float(ql[r0 * 72 + dl]);
            float q1 = __bfloat162float(qh[r1 * 72 + dl]) + __bfloat162float(ql[r1 * 72 + dl]);
            qd0 += q0 * w0;
            qd1 += q1 * w1;
        }
        qd0 += __shfl_xor_sync(0xFFFFFFFFu, qd0, 1); qd0 += __shfl_xor_sync(0xFFFFFFFFu, qd0, 2);
        qd1 += __shfl_xor_sync(0xFFFFFFFFu, qd1, 1); qd1 += __shfl_xor_sync(0xFFFFFFFFu, qd1, 2);
    }
    const float den0 = fmaxf(rs0 + qd0, 1e-6f);
    const float den1 = fmaxf(rs1 + qd1, 1e-6f);

    // ---- write S fragments (split bf16) into K region ----
    __syncthreads();
#pragma unroll
    for (int nt = 0; nt < 8; ++nt) {
        int col = nt * 8 + gc;
        uint32_t hp, lp;
        split2(acc[nt][0], acc[nt][1], hp, lp);
        *reinterpret_cast<uint32_t*>(smc + CW_SH + r0 * ROW2 + col * 2) = hp;
        *reinterpret_cast<uint32_t*>(smc + CW_SL + r0 * ROW2 + col * 2) = lp;
        split2(acc[nt][2], acc[nt][3], hp, lp);
        *reinterpret_cast<uint32_t*>(smc + CW_SH + r1 * ROW2 + col * 2) = hp;
        *reinterpret_cast<uint32_t*>(smc + CW_SL + r1 * ROW2 + col * 2) = lp;
    }
    __syncthreads();

    // ---- accO = S @ V (A = S rows, B = V^T) ----
    float accO[8][4];
#pragma unroll
    for (int nt = 0; nt < 8; ++nt)
#pragma unroll
        for (int e = 0; e < 4; ++e) accO[nt][e] = 0.f;
    for (int ks = 0; ks < 4; ++ks) {
        const int ko = ks * 32;
        uint32_t ah[4], al[4];
        ldsm_x4(ah[0], ah[1], ah[2], ah[3], sbase + CW_SH + aOffQ + ko);
        ldsm_x4(al[0], al[1], al[2], al[3], sbase + CW_SL + aOffQ + ko);
#pragma unroll
        for (int p = 0; p < 4; ++p) {
            uint32_t bh[4], bl[4];
            ldsm_x4(bh[0], bh[1], bh[2], bh[3], sbase + CW_PH + bOff + p * 16 * ROW2 + ko);
            ldsm_x4(bl[0], bl[1], bl[2], bl[3], sbase + CW_PL + bOff + p * 16 * ROW2 + ko);
            mma_bf16(accO[2*p],   ah, bh);     mma_bf16(accO[2*p],   ah, bl);
            mma_bf16(accO[2*p],   al, bh);
            mma_bf16(accO[2*p+1], ah, bh + 2); mma_bf16(accO[2*p+1], ah, bl + 2);
            mma_bf16(accO[2*p+1], al, bh + 2);
        }
    }

    // ---- Q @ P halves (stage P^T split into V^T region, mma, row-scale) ----
    const float4* Pg = reinterpret_cast<const float4*>(g_P + (size_t)(b * NCH + c) * (D2 * HID));
#pragma unroll
    for (int half = 0; half < 2; ++half) {
        __syncthreads();   // previous readers of CW_PH/PL done
        {
            __nv_bfloat16* ph = reinterpret_cast<__nv_bfloat16*>(smc + CW_PH);
            __nv_bfloat16* pl = reinterpret_cast<__nv_bfloat16*>(smc + CW_PL);
            for (int i = tid; i < 1024; i += 128) {
                int dl = i >> 4, mq = i & 15;
                float4 x = Pg[half * 1024 + i];
                float xv[4] = {x.x, x.y, x.z, x.w};
#pragma unroll
                for (int e = 0; e < 4; ++e) {
                    __nv_bfloat16 h, l;
                    splitS(xv[e], h, l);
                    ph[(4 * mq + e) * 72 + dl] = h;
                    pl[(4 * mq + e) * 72 + dl] = l;
                }
            }
        }
        __syncthreads();
        float accT[8][4];
#pragma unroll
        for (int nt = 0; nt < 8; ++nt)
#pragma unroll
            for (int e = 0; e < 4; ++e) accT[nt][e] = 0.f;
        for (int ks = 0; ks < 4; ++ks) {
            const int ko = ks * 32;
            uint32_t ah[4], al[4];
            ldsm_x4(ah[0], ah[1], ah[2], ah[3], sbase + CW_QH + aOffQ + ko);
            ldsm_x4(al[0], al[1], al[2], al[3], sbase + CW_QL + aOffQ + ko);
#pragma unroll
            for (int p = 0; p < 4; ++p) {
                uint32_t bh[4], bl[4];
                ldsm_x4(bh[0], bh[1], bh[2], bh[3], sbase + CW_PH + bOff + p * 16 * ROW2 + ko);
                ldsm_x4(bl[0], bl[1], bl[2], bl[3], sbase + CW_PL + bOff + p * 16 * ROW2 + ko);
                mma_bf16(accT[2*p],   ah, bh);     mma_bf16(accT[2*p],   ah, bl);
                mma_bf16(accT[2*p],   al, bh);
                mma_bf16(accT[2*p+1], ah, bh + 2); mma_bf16(accT[2*p+1], ah, bl + 2);
                mma_bf16(accT[2*p+1], al, bh + 2);
            }
        }
        const float w0 = half ? cr0 : sr0;
        const float w1 = half ? cr1 : sr1;
#pragma unroll
        for (int nt = 0; nt < 8; ++nt) {
            accO[nt][0] += w0 * accT[nt][0];
            accO[nt][1] += w0 * accT[nt][1];
            accO[nt][2] += w1 * accT[nt][2];
            accO[nt][3] += w1 * accT[nt][3];
        }
    }

    // ---- epilogue: divide by denom, split bf16 to g_attnH/L ----
    const float inv0 = 1.0f / den0, inv1 = 1.0f / den1;
    const int n = b >> 3, hh = b & 7;
    const size_t base0 = ((size_t)(c * LCH + r0) * NB + n) * EMB + hh * HID;
    const size_t base1 = ((size_t)(c * LCH + r1) * NB + n) * EMB + hh * HID;
#pragma unroll
    for (int nt = 0; nt < 8; ++nt) {
        int col = nt * 8 + gc;
        uint32_t hp, lp;
        split2(accO[nt][0] * inv0, accO[nt][1] * inv0, hp, lp);
        *reinterpret_cast<uint32_t*>(&g_attnH[base0 + col]) = hp;
        *reinterpret_cast<uint32_t*>(&g_attnL[base0 + col]) = lp;
        split2(accO[nt][2] * inv1, accO[nt][3] * inv1, hp, lp);
        *reinterpret_cast<uint32_t*>(&g_attnH[base1 + col]) = hp;
        *reinterpret_cast<uint32_t*>(&g_attnL[base1 + col]) = lp;
    }
}

// ---------------------------------------------------------------------------
// Kernel D v5: outproj (unchanged from R9, passing)
// ---------------------------------------------------------------------------
#define ROWB 272
#define OAH  0
#define OAL  (OAH + 64 * ROWB)
#define OBH  (OAL + 64 * ROWB)
#define OBL  (OBH + 64 * ROWB)
#define SM_HMMA (OBL + 64 * ROWB)

__global__ __launch_bounds__(128) void outproj_hmma_kernel(const float* __restrict__ bias,
                                                           float* __restrict__ out) {
    extern __shared__ char smc[];
    const uint32_t sbase = smem_u32(smc);
    const int tid = threadIdx.x;
    const int wid = tid >> 5, lane = tid & 31;
    const int rb = blockIdx.x * 64;
    const int nb = blockIdx.y * 64;
    const int wm0 = wid * 16;

    float acc[8][4];
#pragma unroll
    for (int nt = 0; nt < 8; ++nt)
#pragma unroll
        for (int e = 0; e < 4; ++e) acc[nt][e] = 0.f;

    const uint32_t aAddr = sbase + OAH + (wm0 + (lane & 15)) * ROWB + ((lane >> 4) * 8) * 2;
    const uint32_t aAddrL = aAddr + (OAL - OAH);
    const int brow = (lane & 7) + ((lane >> 4) << 3);
    const int bkh  = ((lane >> 3) & 1) * 8;
    const uint32_t bAddr  = sbase + OBH + brow * ROWB + bkh * 2;
    const uint32_t bAddrL = bAddr + (OBL - OBH);

    for (int kc = 0; kc < 4; ++kc) {
        const size_t kbase = (size_t)kc * 128;
        for (int i = tid; i < 1024; i += 128) {
            int r = i >> 4, g = i & 15;
            const uint4* aH = reinterpret_cast<const uint4*>(&g_attnH[(size_t)(rb + r) * EMB + kbase]);
            const uint4* aL = reinterpret_cast<const uint4*>(&g_attnL[(size_t)(rb + r) * EMB + kbase]);
            const uint4* bH = reinterpret_cast<const uint4*>(&g_WH[(size_t)(nb + r) * EMB + kbase]);
            const uint4* bL = reinterpret_cast<const uint4*>(&g_WL[(size_t)(nb + r) * EMB + kbase]);
            char* dst = smc + r * ROWB + g * 16;
            *reinterpret_cast<uint4*>(dst + OAH) = aH[g];
            *reinterpret_cast<uint4*>(dst + OAL) = aL[g];
            *reinterpret_cast<uint4*>(dst + OBH) = bH[g];
            *reinterpret_cast<uint4*>(dst + OBL) = bL[g];
        }
        __syncthreads();

#pragma unroll
        for (int ks = 0; ks < 8; ++ks) {
            const int ko = ks * 32;
            uint32_t ah[4], al[4];
            ldsm_x4(ah[0], ah[1], ah[2], ah[3], aAddr + ko);
            ldsm_x4(al[0], al[1], al[2], al[3], aAddrL + ko);
            uint32_t bh[8][2], bl[8][2];
#pragma unroll
            for (int p = 0; p < 4; ++p) {
                ldsm_x4(bh[2*p][0], bh[2*p][1], bh[2*p+1][0], bh[2*p+1][1],
                        bAddr + p * 16 * ROWB + ko);
                ldsm_x4(bl[2*p][0], bl[2*p][1], bl[2*p+1][0], bl[2*p+1][1],
                        bAddrL + p * 16 * ROWB + ko);
            }
#pragma unroll
            for (int nt = 0; nt < 8; ++nt) {
                mma_bf16(acc[nt], ah, bh[nt]);
                mma_bf16(acc[nt], ah, bl[nt]);
                mma_bf16(acc[nt], al, bh[nt]);
            }
        }
        __syncthreads();
    }

    const int gr = lane >> 2, gc = (lane & 3) * 2;
    const int h = blockIdx.y;
#pragma unroll
    for (int nt = 0; nt < 8; ++nt) {
        int d = nt * 8 + gc;
        float b0 = bias[nb + d], b1 = bias[nb + d + 1];
#pragma unroll
        for (int half = 0; half < 2; ++half) {
            int r = rb + wm0 + gr + half * 8;
            int t = r >> 1, n = r & 1;
            size_t oidx = (((size_t)(n * HH + h) * TT) + t) * HID + d;
            *reinterpret_cast<float2*>(out + oidx) =
                make_float2(acc[nt][half * 2 + 0] + b0,
                            acc[nt][half * 2 + 1] + b1);
        }
    }
}

// ---------------------------------------------------------------------------
// Launch
// ---------------------------------------------------------------------------
extern "C" void kernel_launch(void* const* d_in, const int* in_sizes, int n_in,
                              void* d_out, int out_size) {
    const float* q    = (const float*)d_in[0];
    const float* k    = (const float*)d_in[1];
    const float* v    = (const float*)d_in[2];
    const float* W    = (const float*)d_in[3];
    const float* bias = (const float*)d_in[4];
    float* out = (float*)d_out;

    static cudaStream_t s_side = nullptr;
    static cudaEvent_t evF = nullptr, evJ = nullptr;
    if (!s_side) {
        cudaStreamCreateWithFlags(&s_side, cudaStreamNonBlocking);
        cudaEventCreateWithFlags(&evF, cudaEventDisableTiming);
        cudaEventCreateWithFlags(&evJ, cudaEventDisableTiming);
    }

    cudaFuncSetAttribute(chunk_out_hmma,
                         cudaFuncAttributeMaxDynamicSharedMemorySize, SM_CO);
    cudaFuncSetAttribute(outproj_hmma_kernel,
                         cudaFuncAttributeMaxDynamicSharedMemorySize, SM_HMMA);

    const bool has_probs = (out_size > CTX_ELEMS);
    if (has_probs) {
        cudaEventRecord(evF, 0);
        cudaStreamWaitEvent(s_side, evF, 0);
        cudaMemsetAsync(out + CTX_ELEMS, 0,
                        (size_t)(out_size - CTX_ELEMS) * sizeof(float), s_side);
        cudaEventRecord(evJ, s_side);
    }

    wsplit_kernel<<<64, 256>>>(W);
    chunk_sums_kernel<<<dim3(NHB, NCH), 256, 33280>>>(k, v);
    prefix_kernel<<<dim3(NHB, NCH), 256>>>();
    chunk_out_hmma<<<dim3(NHB, NCH), 128, SM_CO>>>(q, k, v);
    outproj_hmma_kernel<<<dim3(32, 8), 128, SM_HMMA>>>(bias, out);

    if (has_probs) cudaStreamWaitEvent(0, evJ, 0);
}

// round 11
// speedup vs baseline: 1.9445x; 1.0278x over previous
#include <cuda_runtime.h>
#include <cuda_bf16.h>
#include <stdint.h>
#include <math.h>

// Problem constants
#define NB   2
#define HH   8
#define TT   1024
#define HID  64
#define NHB  (NB*HH)
#define D2   (2*HID)
#define EMB  (HH*HID)          // 512
#define LCH  64
#define NCH  (TT/LCH)          // 16
#define CTX_ELEMS (NB*HH*TT*HID)
#define ANG_K 0.0015339807878856412f

typedef unsigned long long u64t;

__device__ __forceinline__ u64t pack2(float lo, float hi) {
    u64t r; asm("mov.b64 %0, {%1, %2};" : "=l"(r) : "f"(lo), "f"(hi)); return r;
}
__device__ __forceinline__ float2 unpack2(u64t p) {
    float2 r; asm("mov.b64 {%0, %1}, %2;" : "=f"(r.x), "=f"(r.y) : "l"(p)); return r;
}
__device__ __forceinline__ void fma2(u64t& d, u64t a, u64t b) {
    asm("fma.rn.f32x2 %0, %1, %2, %0;" : "+l"(d) : "l"(a), "l"(b));
}
__device__ __forceinline__ void mul2(u64t& d, u64t a, u64t b) {
    asm("mul.rn.f32x2 %0, %1, %2;" : "=l"(d) : "l"(a), "l"(b));
}
__device__ __forceinline__ uint32_t smem_u32(const void* p) {
    uint32_t a;
    asm("{ .reg .u64 t; cvta.to.shared.u64 t, %1; cvt.u32.u64 %0, t; }" : "=r"(a) : "l"(p));
    return a;
}

// ---- warp MMA helpers (verified R8-R10) ----
__device__ __forceinline__ void ldsm_x4(uint32_t& r0, uint32_t& r1, uint32_t& r2, uint32_t& r3,
                                        uint32_t addr) {
    asm volatile("ldmatrix.sync.aligned.m8n8.x4.shared.b16 {%0,%1,%2,%3}, [%4];"
                 : "=r"(r0), "=r"(r1), "=r"(r2), "=r"(r3) : "r"(addr));
}
__device__ __forceinline__ void mma_bf16(float* c, const uint32_t* a, const uint32_t* b) {
    asm volatile("mma.sync.aligned.m16n8k16.row.col.f32.bf16.bf16.f32 "
                 "{%0,%1,%2,%3}, {%4,%5,%6,%7}, {%8,%9}, {%0,%1,%2,%3};"
                 : "+f"(c[0]), "+f"(c[1]), "+f"(c[2]), "+f"(c[3])
                 : "r"(a[0]), "r"(a[1]), "r"(a[2]), "r"(a[3]), "r"(b[0]), "r"(b[1]));
}
__device__ __forceinline__ void split4(float4 x, uint32_t& h0, uint32_t& h1,
                                       uint32_t& l0, uint32_t& l1) {
    __nv_bfloat16 a = __float2bfloat16(x.x), b = __float2bfloat16(x.y),
                  c = __float2bfloat16(x.z), d = __float2bfloat16(x.w);
    __nv_bfloat162 hA(a, b), hB(c, d);
    h0 = *reinterpret_cast<uint32_t*>(&hA);
    h1 = *reinterpret_cast<uint32_t*>(&hB);
    __nv_bfloat162 lA(__float2bfloat16(x.x - __bfloat162float(a)),
                      __float2bfloat16(x.y - __bfloat162float(b)));
    __nv_bfloat162 lB(__float2bfloat16(x.z - __bfloat162float(c)),
                      __float2bfloat16(x.w - __bfloat162float(d)));
    l0 = *reinterpret_cast<uint32_t*>(&lA);
    l1 = *reinterpret_cast<uint32_t*>(&lB);
}
__device__ __forceinline__ void split2(float v0, float v1, uint32_t& hp, uint32_t& lp) {
    __nv_bfloat16 h0 = __float2bfloat16(v0), h1 = __float2bfloat16(v1);
    __nv_bfloat162 hv(h0, h1);
    hp = *reinterpret_cast<uint32_t*>(&hv);
    __nv_bfloat162 lv(__float2bfloat16(v0 - __bfloat162float(h0)),
                      __float2bfloat16(v1 - __bfloat162float(h1)));
    lp = *reinterpret_cast<uint32_t*>(&lv);
}
__device__ __forceinline__ void splitS(float v, __nv_bfloat16& h, __nv_bfloat16& l) {
    h = __float2bfloat16(v);
    l = __float2bfloat16(v - __bfloat162float(h));
}

// Scratch (device globals)
// S/P in split-bf16 TRANSPOSED layout [b][c][half][m=64][d=64]
__device__ __align__(16) __nv_bfloat16 g_STH[NHB*NCH*2*64*64];
__device__ __align__(16) __nv_bfloat16 g_STL[NHB*NCH*2*64*64];
__device__ __align__(16) __nv_bfloat16 g_PTH[NHB*NCH*2*64*64];
__device__ __align__(16) __nv_bfloat16 g_PTL[NHB*NCH*2*64*64];
__device__ float g_sk  [NHB*NCH*D2];
__device__ float g_skP [NHB*NCH*D2];
__device__ __align__(16) __nv_bfloat16 g_attnH[TT*NB*EMB];
__device__ __align__(16) __nv_bfloat16 g_attnL[TT*NB*EMB];
__device__ __align__(16) __nv_bfloat16 g_WH[EMB*EMB];
__device__ __align__(16) __nv_bfloat16 g_WL[EMB*EMB];

// ---------------------------------------------------------------------------
// Kernel W: split W (unchanged, passing)
// ---------------------------------------------------------------------------
__global__ __launch_bounds__(256) void wsplit_kernel(const float* __restrict__ W) {
    const int tid = blockIdx.x * 256 + threadIdx.x;
    const float4* W4 = reinterpret_cast<const float4*>(W);
#pragma unroll
    for (int j = 0; j < 4; ++j) {
        int idx = j * 16384 + tid;
        float4 x = W4[idx];
        uint32_t h0, h1, l0, l1;
        split4(x, h0, h1, l0, l1);
        *reinterpret_cast<uint2*>(&g_WH[idx * 4]) = make_uint2(h0, h1);
        *reinterpret_cast<uint2*>(&g_WL[idx * 4]) = make_uint2(l0, l1);
    }
}

// ---------------------------------------------------------------------------
// Kernel A: per-(b,chunk) sums; S written split-bf16 transposed
// ---------------------------------------------------------------------------
__global__ __launch_bounds__(256) void chunk_sums_kernel(const float* __restrict__ k,
                                                         const float* __restrict__ v) {
    extern __shared__ float sm[];
    float* sK   = sm;
    float* sV   = sm + 4096;
    float* sSin = sm + 8192;
    float* sCos = sm + 8256;
    const int b = blockIdx.x, c = blockIdx.y, tid = threadIdx.x;

    if (tid < LCH) {
        float ang = (float)(c * LCH + tid + 1) * ANG_K;
        sSin[tid] = sinf(ang);
        sCos[tid] = cosf(ang);
    }
    const float4* kg = reinterpret_cast<const float4*>(k + ((size_t)b * TT + c * LCH) * HID);
    float4* sK4w = reinterpret_cast<float4*>(sK);
    for (int i = tid; i < LCH * 16; i += 256) {
        float4 kv = kg[i];
        sK4w[i] = make_float4(fmaxf(kv.x, 0.f), fmaxf(kv.y, 0.f),
                              fmaxf(kv.z, 0.f), fmaxf(kv.w, 0.f));
    }
    const float4* vg = reinterpret_cast<const float4*>(v);
    float4* sV4w = reinterpret_cast<float4*>(sV);
    for (int i = tid; i < LCH * 16; i += 256) {
        int t = i >> 4, c4 = i & 15;
        sV4w[t * 16 + c4] = vg[((size_t)(c * LCH + t) * NHB + b) * 16 + c4];
    }
    __syncthreads();

    const int tx = tid & 15, ty = tid >> 4;
    const int m0 = tx * 4;
    const float* wT = (ty < 8) ? sSin : sCos;
    u64t acc[8][2];
#pragma unroll
    for (int i = 0; i < 8; ++i) { acc[i][0] = pack2(0.f, 0.f); acc[i][1] = pack2(0.f, 0.f); }

    const float4* sK4 = reinterpret_cast<const float4*>(sK);
    const float4* sV4 = reinterpret_cast<const float4*>(sV);
    for (int t = 0; t < LCH; ++t) {
        float4 a0 = sK4[t * 16 + (ty & 7) * 2];
        float4 a1 = sK4[t * 16 + (ty & 7) * 2 + 1];
        float4 bv = sV4[t * 16 + tx];
        float w = wT[t];
        u64t wp = pack2(w, w);
        u64t b01 = pack2(bv.x, bv.y), b23 = pack2(bv.z, bv.w);
        mul2(b01, b01, wp);
        mul2(b23, b23, wp);
        float av[8] = {a0.x, a0.y, a0.z, a0.w, a1.x, a1.y, a1.z, a1.w};
#pragma unroll
        for (int i = 0; i < 8; ++i) {
            u64t ad = pack2(av[i], av[i]);
            fma2(acc[i][0], ad, b01);
            fma2(acc[i][1], ad, b23);
        }
    }

    // transposed split store: thread holds 8 d (at draw, half) x 4 m (at m0)
    const int half = ty >> 3;
    const int draw = (ty & 7) * 8;
    const size_t base = ((size_t)((b * NCH + c) * 2 + half)) * 4096;
#pragma unroll
    for (int j = 0; j < 4; ++j) {
        float vals[8];
#pragma unroll
        for (int i = 0; i < 8; ++i) {
            float2 pp = unpack2(acc[i][j >> 1]);
            vals[i] = (j & 1) ? pp.y : pp.x;
        }
        uint32_t hw[4], lw[4];
#pragma unroll
        for (int g = 0; g < 4; ++g) {
            uint32_t hp, lp;
            split2(vals[2 * g], vals[2 * g + 1], hp, lp);
            hw[g] = hp; lw[g] = lp;
        }
        size_t off = base + (size_t)(m0 + j) * 64 + draw;
        *reinterpret_cast<uint4*>(&g_STH[off]) = make_uint4(hw[0], hw[1], hw[2], hw[3]);
        *reinterpret_cast<uint4*>(&g_STL[off]) = make_uint4(lw[0], lw[1], lw[2], lw[3]);
    }

    if (tid < D2) {
        int dl = tid & 63;
        const float* wv = (tid < 64) ? sSin : sCos;
        float s = 0.f;
        for (int t = 0; t < LCH; ++t) s += wv[t] * sK[t * HID + dl];
        g_sk[(b * NCH + c) * D2 + tid] = s;
    }
}

// ---------------------------------------------------------------------------
// Kernel B: exclusive prefix over chunks, split-bf16 in/out
// grid (16,16), 256 thr: each thread owns one bf16x2 pair per b
// ---------------------------------------------------------------------------
__global__ __launch_bounds__(256) void prefix_kernel() {
    const int b = blockIdx.x, s = blockIdx.y, tid = threadIdx.x;
    const int e = s * 256 + tid;           // pair index 0..4095 (8192 elems / 2)
    float r0 = 0.f, r1 = 0.f;
#pragma unroll
    for (int c = 0; c < NCH; ++c) {
        size_t idx = ((size_t)(b * NCH + c)) * 8192 + (size_t)e * 2;
        uint32_t hp, lp;
        split2(r0, r1, hp, lp);
        *reinterpret_cast<uint32_t*>(&g_PTH[idx]) = hp;
        *reinterpret_cast<uint32_t*>(&g_PTL[idx]) = lp;
        uint32_t hs = *reinterpret_cast<const uint32_t*>(&g_STH[idx]);
        uint32_t ls = *reinterpret_cast<const uint32_t*>(&g_STL[idx]);
        __nv_bfloat162 h2 = *reinterpret_cast<__nv_bfloat162*>(&hs);
        __nv_bfloat162 l2 = *reinterpret_cast<__nv_bfloat162*>(&ls);
        r0 += __bfloat162float(h2.x) + __bfloat162float(l2.x);
        r1 += __bfloat162float(h2.y) + __bfloat162float(l2.y);
    }
    if (s == 0 && tid < D2) {
        float run = 0.f;
#pragma unroll
        for (int c = 0; c < NCH; ++c) {
            int idx = (b * NCH + c) * D2 + tid;
            g_skP[idx] = run;
            run += g_sk[idx];
        }
    }
}

// ---------------------------------------------------------------------------
// Kernel C v3: chunk output via mma.sync bf16x3, 256 thr (4 m-warps x 2 n-halves)
// P staged with pure uint4 copies (pre-split, pre-transposed)
// ---------------------------------------------------------------------------
#define ROW2 144
#define CW_QH 0
#define CW_QL 9216
#define CW_SH 18432              // K, then S
#define CW_SL 27648
#define CW_PH 36864              // V^T, then P^T halves
#define CW_PL 46080
#define CW_FLT 55296             // sin64 cos64 skp128 rs128 den64 = 448 f
#define SM_CO (CW_FLT + 1792)

__global__ __launch_bounds__(256, 2) void chunk_out_hmma(const float* __restrict__ q,
                                                         const float* __restrict__ k,
                                                         const float* __restrict__ v) {
    extern __shared__ char smc[];
    const uint32_t sbase = smem_u32(smc);
    const int tid = threadIdx.x;
    const int wid = tid >> 5, lane = tid & 31;
    const int wm = wid & 3, wn = wid >> 2;
    const int b = blockIdx.x, c = blockIdx.y;

    float* sF = reinterpret_cast<float*>(smc + CW_FLT);
    if (tid < 64) {
        float ang = (float)(c * LCH + tid + 1) * ANG_K;
        sF[tid] = sinf(ang);
        sF[64 + tid] = cosf(ang);
    }
    if (tid < 128) sF[128 + tid] = g_skP[(b * NCH + c) * D2 + tid];

    // ---- stage Q, K (relu, split) ----
    const float4* qg = reinterpret_cast<const float4*>(q + ((size_t)b * TT + c * LCH) * HID);
    const float4* kg = reinterpret_cast<const float4*>(k + ((size_t)b * TT + c * LCH) * HID);
    for (int i = tid; i < 1024; i += 256) {
        int t = i >> 4, c4 = i & 15;
        float4 qv = qg[i];
        qv = make_float4(fmaxf(qv.x, 0.f), fmaxf(qv.y, 0.f), fmaxf(qv.z, 0.f), fmaxf(qv.w, 0.f));
        uint32_t h0, h1, l0, l1;
        split4(qv, h0, h1, l0, l1);
        *reinterpret_cast<uint2*>(smc + CW_QH + t * ROW2 + c4 * 8) = make_uint2(h0, h1);
        *reinterpret_cast<uint2*>(smc + CW_QL + t * ROW2 + c4 * 8) = make_uint2(l0, l1);
        float4 kv = kg[i];
        kv = make_float4(fmaxf(kv.x, 0.f), fmaxf(kv.y, 0.f), fmaxf(kv.z, 0.f), fmaxf(kv.w, 0.f));
        split4(kv, h0, h1, l0, l1);
        *reinterpret_cast<uint2*>(smc + CW_SH + t * ROW2 + c4 * 8) = make_uint2(h0, h1);
        *reinterpret_cast<uint2*>(smc + CW_SL + t * ROW2 + c4 * 8) = make_uint2(l0, l1);
    }
    // ---- stage V^T (split, transposed) ----
    {
        const float4* vg = reinterpret_cast<const float4*>(v);
        __nv_bfloat16* vh = reinterpret_cast<__nv_bfloat16*>(smc + CW_PH);
        __nv_bfloat16* vl = reinterpret_cast<__nv_bfloat16*>(smc + CW_PL);
        for (int i = tid; i < 1024; i += 256) {
            int tp = i >> 4, mq = i & 15;
            float4 x = vg[((size_t)(c * LCH + tp) * NHB + b) * 16 + mq];
            float xv[4] = {x.x, x.y, x.z, x.w};
#pragma unroll
            for (int e = 0; e < 4; ++e) {
                __nv_bfloat16 h, l;
                splitS(xv[e], h, l);
                vh[(4 * mq + e) * 72 + tp] = h;
                vl[(4 * mq + e) * 72 + tp] = l;
            }
        }
    }
    __syncthreads();

    const uint32_t aOffQ = (uint32_t)((wm * 16 + (lane & 15)) * ROW2 + ((lane >> 4) * 8) * 2);
    const uint32_t bOffB = (uint32_t)(((lane & 7) + ((lane >> 4) << 3)) * ROW2 +
                                      (((lane >> 3) & 1) * 8) * 2);

    // ---- score: acc = Q K^T, causal tile skip ----
    float acc[4][4];
#pragma unroll
    for (int j = 0; j < 4; ++j)
#pragma unroll
        for (int e = 0; e < 4; ++e) acc[j][e] = 0.f;
    for (int ks = 0; ks < 4; ++ks) {
        const int ko = ks * 32;
        uint32_t ah[4], al[4];
        ldsm_x4(ah[0], ah[1], ah[2], ah[3], sbase + CW_QH + aOffQ + ko);
        ldsm_x4(al[0], al[1], al[2], al[3], sbase + CW_QL + aOffQ + ko);
#pragma unroll
        for (int pl = 0; pl < 2; ++pl) {
            const int p = wn * 2 + pl;
            if (p > wm) continue;
            uint32_t bh[4], bl[4];
            ldsm_x4(bh[0], bh[1], bh[2], bh[3], sbase + CW_SH + bOffB + p * 16 * ROW2 + ko);
            ldsm_x4(bl[0], bl[1], bl[2], bl[3], sbase + CW_SL + bOffB + p * 16 * ROW2 + ko);
            mma_bf16(acc[2*pl],   ah, bh);     mma_bf16(acc[2*pl],   ah, bl);
            mma_bf16(acc[2*pl],   al, bh);
            mma_bf16(acc[2*pl+1], ah, bh + 2); mma_bf16(acc[2*pl+1], ah, bl + 2);
            mma_bf16(acc[2*pl+1], al, bh + 2);
        }
    }

    // ---- factor + mask + partial rowsums ----
    const int gr = lane >> 2, gc = (lane & 3) * 2;
    const int r0 = wm * 16 + gr, r1 = r0 + 8;
    const float sr0 = sF[r0], cr0 = sF[64 + r0];
    const float sr1 = sF[r1], cr1 = sF[64 + r1];
    float rs0 = 0.f, rs1 = 0.f;
#pragma unroll
    for (int j = 0; j < 4; ++j) {
        int c0 = wn * 32 + j * 8 + gc, c1 = c0 + 1;
        float sc0 = sF[c0], cc0 = sF[64 + c0], sc1 = sF[c1], cc1 = sF[64 + c1];
        acc[j][0] = (c0 <= r0) ? acc[j][0] * (cr0 * cc0 + sr0 * sc0) : 0.f;
        acc[j][1] = (c1 <= r0) ? acc[j][1] * (cr0 * cc1 + sr0 * sc1) : 0.f;
        acc[j][2] = (c0 <= r1) ? acc[j][2] * (cr1 * cc0 + sr1 * sc0) : 0.f;
        acc[j][3] = (c1 <= r1) ? acc[j][3] * (cr1 * cc1 + sr1 * sc1) : 0.f;
        rs0 += acc[j][0] + acc[j][1];
        rs1 += acc[j][2] + acc[j][3];
    }
    rs0 += __shfl_xor_sync(0xFFFFFFFFu, rs0, 1); rs0 += __shfl_xor_sync(0xFFFFFFFFu, rs0, 2);
    rs1 += __shfl_xor_sync(0xFFFFFFFFu, rs1, 1); rs1 += __shfl_xor_sync(0xFFFFFFFFu, rs1, 2);
    if ((lane & 3) == 0) {
        sF[256 + wn * 64 + r0] = rs0;
        sF[256 + wn * 64 + r1] = rs1;
    }
    __syncthreads();   // K reads done; rowsum partials visible

    // ---- write S fragments into K region ----
#pragma unroll
    for (int j = 0; j < 4; ++j) {
        int col = wn * 32 + j * 8 + gc;
        uint32_t hp, lp;
        split2(acc[j][0], acc[j][1], hp, lp);
        *reinterpret_cast<uint32_t*>(smc + CW_SH + r0 * ROW2 + col * 2) = hp;
        *reinterpret_cast<uint32_t*>(smc + CW_SL + r0 * ROW2 + col * 2) = lp;
        split2(acc[j][2], acc[j][3], hp, lp);
        *reinterpret_cast<uint32_t*>(smc + CW_SH + r1 * ROW2 + col * 2) = hp;
        *reinterpret_cast<uint32_t*>(smc + CW_SL + r1 * ROW2 + col * 2) = lp;
    }
    // ---- denominator (wn==0 warps) ----
    if (wn == 0) {
        float qd0 = 0.f, qd1 = 0.f;
        const __nv_bfloat16* qh = reinterpret_cast<const __nv_bfloat16*>(smc + CW_QH);
        const __nv_bfloat16* ql = reinterpret_cast<const __nv_bfloat16*>(smc + CW_QL);
        const int d0 = (lane & 3) * 16;
#pragma unroll
        for (int j = 0; j < 16; ++j) {
            int dl = d0 + j;
            float w0 = sr0 * sF[128 + dl] + cr0 * sF[192 + dl];
            float w1 = sr1 * sF[128 + dl] + cr1 * sF[192 + dl];
            float q0 = __bfloat162float(qh[r0 * 72 + dl]) + __bfloat162float(ql[r0 * 72 + dl]);
            float q1 = __bfloat162float(qh[r1 * 72 + dl]) + __bfloat162float(ql[r1 * 72 + dl]);
            qd0 += q0 * w0;
            qd1 += q1 * w1;
        }
        qd0 += __shfl_xor_sync(0xFFFFFFFFu, qd0, 1); qd0 += __shfl_xor_sync(0xFFFFFFFFu, qd0, 2);
        qd1 += __shfl_xor_sync(0xFFFFFFFFu, qd1, 1); qd1 += __shfl_xor_sync(0xFFFFFFFFu, qd1, 2);
        if ((lane & 3) == 0) {
            sF[384 + r0] = fmaxf(sF[256 + r0] + sF[320 + r0] + qd0, 1e-6f);
            sF[384 + r1] = fmaxf(sF[256 + r1] + sF[320 + r1] + qd1, 1e-6f);
        }
    }
    __syncthreads();   // S frags + den visible

    // ---- accO = S @ V ----
    float accO[4][4];
#pragma unroll
    for (int j = 0; j < 4; ++j)
#pragma unroll
        for (int e = 0; e < 4; ++e) accO[j][e] = 0.f;
    for (int ks = 0; ks < 4; ++ks) {
        const int ko = ks * 32;
        uint32_t ah[4], al[4];
        ldsm_x4(ah[0], ah[1], ah[2], ah[3], sbase + CW_SH + aOffQ + ko);
        ldsm_x4(al[0], al[1], al[2], al[3], sbase + CW_SL + aOffQ + ko);
#pragma unroll
        for (int pl = 0; pl < 2; ++pl) {
            const int p = wn * 2 + pl;
            uint32_t bh[4], bl[4];
            ldsm_x4(bh[0], bh[1], bh[2], bh[3], sbase + CW_PH + bOffB + p * 16 * ROW2 + ko);
            ldsm_x4(bl[0], bl[1], bl[2], bl[3], sbase + CW_PL + bOffB + p * 16 * ROW2 + ko);
            mma_bf16(accO[2*pl],   ah, bh);     mma_bf16(accO[2*pl],   ah, bl);
            mma_bf16(accO[2*pl],   al, bh);
            mma_bf16(accO[2*pl+1], ah, bh + 2); mma_bf16(accO[2*pl+1], ah, bl + 2);
            mma_bf16(accO[2*pl+1], al, bh + 2);
        }
    }

    // ---- Q @ P halves (pre-split transposed P -> pure uint4 staging) ----
    const size_t basePT = ((size_t)((b * NCH + c) * 2)) * 4096;
#pragma unroll
    for (int half = 0; half < 2; ++half) {
        __syncthreads();   // prior PH/PL readers done
        for (int i = tid; i < 512; i += 256) {
            int row = i >> 3, g = i & 7;
            size_t off = basePT + (size_t)half * 4096 + (size_t)row * 64 + g * 8;
            *reinterpret_cast<uint4*>(smc + CW_PH + row * ROW2 + g * 16) =
                *reinterpret_cast<const uint4*>(&g_PTH[off]);
            *reinterpret_cast<uint4*>(smc + CW_PL + row * ROW2 + g * 16) =
                *reinterpret_cast<const uint4*>(&g_PTL[off]);
        }
        __syncthreads();
        float accT[4][4];
#pragma unroll
        for (int j = 0; j < 4; ++j)
#pragma unroll
            for (int e = 0; e < 4; ++e) accT[j][e] = 0.f;
        for (int ks = 0; ks < 4; ++ks) {
            const int ko = ks * 32;
            uint32_t ah[4], al[4];
            ldsm_x4(ah[0], ah[1], ah[2], ah[3], sbase + CW_QH + aOffQ + ko);
            ldsm_x4(al[0], al[1], al[2], al[3], sbase + CW_QL + aOffQ + ko);
#pragma unroll
            for (int pl = 0; pl < 2; ++pl) {
                const int p = wn * 2 + pl;
                uint32_t bh[4], bl[4];
                ldsm_x4(bh[0], bh[1], bh[2], bh[3], sbase + CW_PH + bOffB + p * 16 * ROW2 + ko);
                ldsm_x4(bl[0], bl[1], bl[2], bl[3], sbase + CW_PL + bOffB + p * 16 * ROW2 + ko);
                mma_bf16(accT[2*pl],   ah, bh);     mma_bf16(accT[2*pl],   ah, bl);
                mma_bf16(accT[2*pl],   al, bh);
                mma_bf16(accT[2*pl+1], ah, bh + 2); mma_bf16(accT[2*pl+1], ah, bl + 2);
                mma_bf16(accT[2*pl+1], al, bh + 2);
            }
        }
        const float w0 = half ? cr0 : sr0;
        const float w1 = half ? cr1 : sr1;
#pragma unroll
        for (int j = 0; j < 4; ++j) {
            accO[j][0] += w0 * accT[j][0];
            accO[j][1] += w0 * accT[j][1];
            accO[j][2] += w1 * accT[j][2];
            accO[j][3] += w1 * accT[j][3];
        }
    }

    // ---- epilogue ----
    const float inv0 = 1.0f / sF[384 + r0], inv1 = 1.0f / sF[384 + r1];
    const int n = b >> 3, hh = b & 7;
    const size_t base0 = ((size_t)(c * LCH + r0) * NB + n) * EMB + hh * HID;
    const size_t base1 = ((size_t)(c * LCH + r1) * NB + n) * EMB + hh * HID;
#pragma unroll
    for (int j = 0; j < 4; ++j) {
        int col = wn * 32 + j * 8 + gc;
        uint32_t hp, lp;
        split2(accO[j][0] * inv0, accO[j][1] * inv0, hp, lp);
        *reinterpret_cast<uint32_t*>(&g_attnH[base0 + col]) = hp;
        *reinterpret_cast<uint32_t*>(&g_attnL[base0 + col]) = lp;
        split2(accO[j][2] * inv1, accO[j][3] * inv1, hp, lp);
        *reinterpret_cast<uint32_t*>(&g_attnH[base1 + col]) = hp;
        *reinterpret_cast<uint32_t*>(&g_attnL[base1 + col]) = lp;
    }
}

// ---------------------------------------------------------------------------
// Kernel D v5: outproj (unchanged from R9/R10, passing)
// ---------------------------------------------------------------------------
#define ROWB 272
#define OAH  0
#define OAL  (OAH + 64 * ROWB)
#define OBH  (OAL + 64 * ROWB)
#define OBL  (OBH + 64 * ROWB)
#define SM_HMMA (OBL + 64 * ROWB)

__global__ __launch_bounds__(128) void outproj_hmma_kernel(const float* __restrict__ bias,
                                                           float* __restrict__ out) {
    extern __shared__ char smc[];
    const uint32_t sbase = smem_u32(smc);
    const int tid = threadIdx.x;
    const int wid = tid >> 5, lane = tid & 31;
    const int rb = blockIdx.x * 64;
    const int nb = blockIdx.y * 64;
    const int wm0 = wid * 16;

    float acc[8][4];
#pragma unroll
    for (int nt = 0; nt < 8; ++nt)
#pragma unroll
        for (int e = 0; e < 4; ++e) acc[nt][e] = 0.f;

    const uint32_t aAddr = sbase + OAH + (wm0 + (lane & 15)) * ROWB + ((lane >> 4) * 8) * 2;
    const uint32_t aAddrL = aAddr + (OAL - OAH);
    const int brow = (lane & 7) + ((lane >> 4) << 3);
    const int bkh  = ((lane >> 3) & 1) * 8;
    const uint32_t bAddr  = sbase + OBH + brow * ROWB + bkh * 2;
    const uint32_t bAddrL = bAddr + (OBL - OBH);

    for (int kc = 0; kc < 4; ++kc) {
        const size_t kbase = (size_t)kc * 128;
        for (int i = tid; i < 1024; i += 128) {
            int r = i >> 4, g = i & 15;
            const uint4* aH = reinterpret_cast<const uint4*>(&g_attnH[(size_t)(rb + r) * EMB + kbase]);
            const uint4* aL = reinterpret_cast<const uint4*>(&g_attnL[(size_t)(rb + r) * EMB + kbase]);
            const uint4* bH = reinterpret_cast<const uint4*>(&g_WH[(size_t)(nb + r) * EMB + kbase]);
            const uint4* bL = reinterpret_cast<const uint4*>(&g_WL[(size_t)(nb + r) * EMB + kbase]);
            char* dst = smc + r * ROWB + g * 16;
            *reinterpret_cast<uint4*>(dst + OAH) = aH[g];
            *reinterpret_cast<uint4*>(dst + OAL) = aL[g];
            *reinterpret_cast<uint4*>(dst + OBH) = bH[g];
            *reinterpret_cast<uint4*>(dst + OBL) = bL[g];
        }
        __syncthreads();

#pragma unroll
        for (int ks = 0; ks < 8; ++ks) {
            const int ko = ks * 32;
            uint32_t ah[4], al[4];
            ldsm_x4(ah[0], ah[1], ah[2], ah[3], aAddr + ko);
            ldsm_x4(al[0], al[1], al[2], al[3], aAddrL + ko);
            uint32_t bh[8][2], bl[8][2];
#pragma unroll
            for (int p = 0; p < 4; ++p) {
                ldsm_x4(bh[2*p][0], bh[2*p][1], bh[2*p+1][0], bh[2*p+1][1],
                        bAddr + p * 16 * ROWB + ko);
                ldsm_x4(bl[2*p][0], bl[2*p][1], bl[2*p+1][0], bl[2*p+1][1],
                        bAddrL + p * 16 * ROWB + ko);
            }
#pragma unroll
            for (int nt = 0; nt < 8; ++nt) {
                mma_bf16(acc[nt], ah, bh[nt]);
                mma_bf16(acc[nt], ah, bl[nt]);
                mma_bf16(acc[nt], al, bh[nt]);
            }
        }
        __syncthreads();
    }

    const int gr = lane >> 2, gc = (lane & 3) * 2;
    const int h = blockIdx.y;
#pragma unroll
    for (int nt = 0; nt < 8; ++nt) {
        int d = nt * 8 + gc;
        float b0 = bias[nb + d], b1 = bias[nb + d + 1];
#pragma unroll
        for (int half = 0; half < 2; ++half) {
            int r = rb + wm0 + gr + half * 8;
            int t = r >> 1, n = r & 1;
            size_t oidx = (((size_t)(n * HH + h) * TT) + t) * HID + d;
            *reinterpret_cast<float2*>(out + oidx) =
                make_float2(acc[nt][half * 2 + 0] + b0,
                            acc[nt][half * 2 + 1] + b1);
        }
    }
}

// ---------------------------------------------------------------------------
// Launch
// ---------------------------------------------------------------------------
extern "C" void kernel_launch(void* const* d_in, const int* in_sizes, int n_in,
                              void* d_out, int out_size) {
    const float* q    = (const float*)d_in[0];
    const float* k    = (const float*)d_in[1];
    const float* v    = (const float*)d_in[2];
    const float* W    = (const float*)d_in[3];
    const float* bias = (const float*)d_in[4];
    float* out = (float*)d_out;

    static cudaStream_t s_side = nullptr;
    static cudaEvent_t evF = nullptr, evJ = nullptr;
    if (!s_side) {
        cudaStreamCreateWithFlags(&s_side, cudaStreamNonBlocking);
        cudaEventCreateWithFlags(&evF, cudaEventDisableTiming);
        cudaEventCreateWithFlags(&evJ, cudaEventDisableTiming);
    }

    cudaFuncSetAttribute(chunk_out_hmma,
                         cudaFuncAttributeMaxDynamicSharedMemorySize, SM_CO);
    cudaFuncSetAttribute(outproj_hmma_kernel,
                         cudaFuncAttributeMaxDynamicSharedMemorySize, SM_HMMA);

    const bool has_probs = (out_size > CTX_ELEMS);
    if (has_probs) {
        cudaEventRecord(evF, 0);
        cudaStreamWaitEvent(s_side, evF, 0);
        cudaMemsetAsync(out + CTX_ELEMS, 0,
                        (size_t)(out_size - CTX_ELEMS) * sizeof(float), s_side);
        cudaEventRecord(evJ, s_side);
    }

    wsplit_kernel<<<64, 256>>>(W);
    chunk_sums_kernel<<<dim3(NHB, NCH), 256, 33280>>>(k, v);
    prefix_kernel<<<dim3(NHB, NCH), 256>>>();
    chunk_out_hmma<<<dim3(NHB, NCH), 256, SM_CO>>>(q, k, v);
    outproj_hmma_kernel<<<dim3(32, 8), 128, SM_HMMA>>>(bias, out);

    if (has_probs) cudaStreamWaitEvent(0, evJ, 0);
}